// round 12
// baseline (speedup 1.0000x reference)
#include <cuda_runtime.h>
#include <cuda_bf16.h>
#include <cstdint>

#define NB 1024

// fp32 buffers (zero-init device globals; pad rows never written)
__device__ float g_bx[7 * 130048];
__device__ float g_b0[5 * 650240];   // t0 conv0a out
__device__ float g_b2[5 * 82944];    // t2 Wr0 out
__device__ float g_x2[150 * 209920]; // x2 (Wa out, acc target)
__device__ float g_b9[512 * 55296];  // final pre-transpose

// bf16 hi/lo activations
__device__ __align__(16) __nv_bfloat16 g_bxh[7 * 130048],  g_bxl[7 * 130048];
__device__ __align__(16) __nv_bfloat16 g_t0h[5 * 650240],  g_t0l[5 * 650240];
__device__ __align__(16) __nv_bfloat16 g_t1h[5 * 580608],  g_t1l[5 * 580608];
__device__ __align__(16) __nv_bfloat16 g_x1h[25 * 580608], g_x1l[25 * 580608];
__device__ __align__(16) __nv_bfloat16 g_t3h[75 * 414720], g_t3l[75 * 414720];
__device__ __align__(16) __nv_bfloat16 g_t4h[75 * 293888], g_t4l[75 * 293888];
__device__ __align__(16) __nv_bfloat16 g_t5h[25 * 209920], g_t5l[25 * 209920];
__device__ __align__(16) __nv_bfloat16 g_x2h[150 * 209920], g_x2l[150 * 209920];
__device__ __align__(16) __nv_bfloat16 g_t6h[300 * 167936], g_t6l[300 * 167936];
__device__ __align__(16) __nv_bfloat16 g_t7h[300 * 73728], g_t7l[300 * 73728];
__device__ __align__(16) __nv_bfloat16 g_t8h[150 * 92160], g_t8l[150 * 92160];
// bf16 hi/lo weights (K padded to mult 16)
__device__ __align__(16) __nv_bfloat16 g_w1h[75 * 80],    g_w1l[75 * 80];
__device__ __align__(16) __nv_bfloat16 g_w2h[150 * 240],  g_w2l[150 * 240];
__device__ __align__(16) __nv_bfloat16 g_w3h[300 * 304],  g_w3l[300 * 304];
__device__ __align__(16) __nv_bfloat16 g_w4h[512 * 608],  g_w4l[512 * 608];
__device__ __align__(16) __nv_bfloat16 g_wbh[512 * 464],  g_wbl[512 * 464];
__device__ __align__(16) __nv_bfloat16 g_wl0h[81 * 128],  g_wl0l[81 * 128];
__device__ __align__(16) __nv_bfloat16 g_wr0h[81 * 128],  g_wr0l[81 * 128];
__device__ __align__(16) __nv_bfloat16 g_w0bh[25 * 16],   g_w0bl[25 * 16];
__device__ __align__(16) __nv_bfloat16 g_wl1h[41 * 96],   g_wl1l[41 * 96];
__device__ __align__(16) __nv_bfloat16 g_wrah[41 * 96],   g_wral[41 * 96];
__device__ __align__(16) __nv_bfloat16 g_wah[150 * 32],   g_wal[150 * 32];
__device__ __align__(16) __nv_bfloat16 g_wl2h[18 * 48],   g_wl2l[18 * 48];
__device__ __align__(16) __nv_bfloat16 g_wrbh[18 * 48],   g_wrbl[18 * 48];

__device__ __forceinline__ uint32_t s2u(const void* p) {
    uint32_t a;
    asm("{ .reg .u64 t; cvta.to.shared.u64 t, %1; cvt.u32.u64 %0, t; }" : "=r"(a) : "l"(p));
    return a;
}
#define SW128(o) ((o) ^ (((o) >> 3) & 0x70))
#define CP16(d, s) asm volatile("cp.async.cg.shared.global [%0], [%1], 16;" :: "r"(d), "l"(s))
__device__ __forceinline__ void zsts16(uint32_t d) {
    asm volatile("st.shared.v4.b32 [%0], {%1,%1,%1,%1};" :: "r"(d), "r"(0u));
}
#define LDMX4(r, a) \
    asm volatile("ldmatrix.sync.aligned.m8n8.x4.shared.b16 {%0,%1,%2,%3}, [%4];" \
        : "=r"((r)[0]), "=r"((r)[1]), "=r"((r)[2]), "=r"((r)[3]) : "r"(a))
#define LDMX4T(r, a) \
    asm volatile("ldmatrix.sync.aligned.m8n8.x4.trans.shared.b16 {%0,%1,%2,%3}, [%4];" \
        : "=r"((r)[0]), "=r"((r)[1]), "=r"((r)[2]), "=r"((r)[3]) : "r"(a))
#define MMA16816(c, a, b0, b1) \
    asm volatile("mma.sync.aligned.m16n8k16.row.col.f32.bf16.bf16.f32 " \
        "{%0,%1,%2,%3},{%4,%5,%6,%7},{%8,%9},{%0,%1,%2,%3};" \
        : "+f"((c)[0]), "+f"((c)[1]), "+f"((c)[2]), "+f"((c)[3]) \
        : "r"((a)[0]), "r"((a)[1]), "r"((a)[2]), "r"((a)[3]), "r"(b0), "r"(b1))

#define F_ACC  1
#define F_RELU 2
#define F_F32  4
#define F_HL   8
#define F_OUT  16

struct TP {
    const __nv_bfloat16 *Ah, *Al, *Xh, *Xl;
    const float* bias;
    float* C;
    __nv_bfloat16 *Ch, *Cl;
    const float* Y;
    const float* osc;
    const float* bias2;
    int M, K, Kp, KH, Hdiv, NC, flags;
    long long s_i, s_dh, xz_c, xz_h, cz_c, cz_h, c_ld;
};

__device__ __forceinline__ void tg_epi(const TP& p, float v0, float v1,
                                       long long rb, int n) {
    if (p.flags & F_F32)
        *reinterpret_cast<float2*>(&p.C[rb + n]) = make_float2(v0, v1);
    if (p.flags & F_HL) {
        __nv_bfloat16 h0 = __float2bfloat16(v0), h1 = __float2bfloat16(v1);
        __nv_bfloat162 hh; hh.x = h0; hh.y = h1;
        __nv_bfloat162 ll;
        ll.x = __float2bfloat16(v0 - __bfloat162float(h0));
        ll.y = __float2bfloat16(v1 - __bfloat162float(h1));
        *reinterpret_cast<__nv_bfloat162*>(&p.Ch[rb + n]) = hh;
        *reinterpret_cast<__nv_bfloat162*>(&p.Cl[rb + n]) = ll;
    }
}

// ---- 512-thread kernel: CTA (32*MI)m x 256n x 64k, 16 warps as 2m x 8n ------
template<int MI>
__global__ __launch_bounds__(512) void tg512n_k(TP p) {
    constexpr int A_HALF = MI * 4096;
    constexpr int XOFF = 2 * A_HALF;
    constexpr int STAGE = XOFF + 65536;    // X: 64k x 256n x 2B x 2 halves
    extern __shared__ char sm_raw[];
    const uint32_t smb = s2u(sm_raw);
    const int tid = threadIdx.x;
    const int lane = tid & 31;
    const int warp_m = (tid >> 5) >> 3;    // 0..1
    const int warp_n = (tid >> 5) & 7;     // 0..7

    const int m0 = blockIdx.y * (MI * 32);
    const long long n0 = (long long)blockIdx.x * 256;
    const int zc = blockIdx.z / p.Hdiv, zh = blockIdx.z % p.Hdiv;
    const long long xzb = (long long)zc * p.xz_c + (long long)zh * p.xz_h;

    auto load_chunk = [&](int c, int b) {
        const uint32_t base = smb + b * STAGE;
        const int kc = c * 64;
#pragma unroll
        for (int i = 0; i < MI; i++) {                 // A: MI*512 x 16B chunks
            int idx = tid + i * 512;
            int half = idx / (MI * 256), r = idx % (MI * 256);
            int m = r >> 3, k16 = r & 7;
            int gm = m0 + m, gk = kc + k16 * 8;
            uint32_t dst = base + half * A_HALF + SW128(m * 128 + k16 * 16);
            if (gm < p.M && gk < p.Kp)
                CP16(dst, (half ? p.Al : p.Ah) + (long long)gm * p.Kp + gk);
            else zsts16(dst);
        }
#pragma unroll
        for (int i = 0; i < 8; i++) {                  // X: 4096 x 16B chunks
            int idx = tid + i * 512;
            int half = idx >> 11, r = idx & 2047;
            int nblk = r >> 9, k = (r >> 3) & 63, n16 = r & 7;
            int gk = kc + k;
            uint32_t dst = base + XOFF + half * 32768 + nblk * 8192 + SW128(k * 128 + n16 * 16);
            if (gk < p.K) {
                long long ro = (long long)(gk / p.KH) * p.s_i + (long long)(gk % p.KH) * p.s_dh;
                CP16(dst, (half ? p.Xl : p.Xh) + xzb + ro + n0 + nblk * 64 + n16 * 8);
            } else zsts16(dst);
        }
        asm volatile("cp.async.commit_group;" ::: "memory");
    };

    float acc[MI][4][4];
#pragma unroll
    for (int a = 0; a < MI; a++)
#pragma unroll
        for (int b = 0; b < 4; b++)
#pragma unroll
            for (int r = 0; r < 4; r++) acc[a][b][r] = 0.f;

    load_chunk(0, 0);

    const int a_row = warp_m * (MI * 16) + (lane & 15);
    const int a_kb  = (lane >> 4) * 16;
    const int b_grp = lane >> 3, b_lr = lane & 7;
    const int b_k0  = (b_grp & 1) * 8 + b_lr;
    const int b_n   = warp_n * 32 + (b_grp >> 1) * 8;
    const int b_nblk = b_n >> 6, b_nin = b_n & 63;

    for (int c = 0; c < p.NC; c++) {
        if (c + 1 < p.NC) {
            load_chunk(c + 1, (c + 1) & 1);
            asm volatile("cp.async.wait_group 1;" ::: "memory");
        } else {
            asm volatile("cp.async.wait_group 0;" ::: "memory");
        }
        __syncthreads();
        const uint32_t base = smb + (c & 1) * STAGE;
#pragma unroll
        for (int s = 0; s < 4; s++) {
            uint32_t af[2][MI][4];
            uint32_t bf[2][2][4];
#pragma unroll
            for (int h = 0; h < 2; h++)
#pragma unroll
                for (int mi = 0; mi < MI; mi++) {
                    uint32_t ad = base + h * A_HALF
                        + SW128((a_row + mi * 16) * 128 + s * 32 + a_kb);
                    LDMX4(af[h][mi], ad);
                }
#pragma unroll
            for (int h = 0; h < 2; h++)
#pragma unroll
                for (int nj = 0; nj < 2; nj++) {
                    uint32_t ad = base + XOFF + h * 32768 + b_nblk * 8192
                        + SW128((s * 16 + b_k0) * 128 + (b_nin + nj * 16) * 2);
                    LDMX4T(bf[h][nj], ad);
                }
#pragma unroll
            for (int mi = 0; mi < MI; mi++)
#pragma unroll
                for (int n8 = 0; n8 < 4; n8++) {
                    int nj = n8 >> 1, pr = (n8 & 1) * 2;
                    MMA16816(acc[mi][n8], af[0][mi], bf[0][nj][pr], bf[0][nj][pr + 1]);
                    MMA16816(acc[mi][n8], af[0][mi], bf[1][nj][pr], bf[1][nj][pr + 1]);
                    MMA16816(acc[mi][n8], af[1][mi], bf[0][nj][pr], bf[0][nj][pr + 1]);
                }
        }
        __syncthreads();
    }

    const int g = lane >> 2, t4i = lane & 3;
    const long long czb = (long long)zc * p.cz_c + (long long)zh * p.cz_h + n0;
#pragma unroll
    for (int mi = 0; mi < MI; mi++)
#pragma unroll
        for (int part = 0; part < 2; part++) {
            int gm = m0 + warp_m * (MI * 16) + mi * 16 + g + part * 8;
            if (gm >= p.M) continue;
            float bs = p.bias[gm];
            float ow = 0.f;
            if (p.flags & F_OUT) { bs += p.bias2[gm]; ow = p.osc[gm]; }
            long long rb = czb + (long long)gm * p.c_ld;
#pragma unroll
            for (int n8 = 0; n8 < 4; n8++) {
                int n = warp_n * 32 + n8 * 8 + t4i * 2;
                float v0 = acc[mi][n8][part * 2] + bs;
                float v1 = acc[mi][n8][part * 2 + 1] + bs;
                if (p.flags & F_OUT) {
                    float2 y = *reinterpret_cast<const float2*>(&p.Y[czb + n]);
                    v0 += ow * y.x; v1 += ow * y.y;
                }
                if (p.flags & F_ACC) {
                    float2 o = *reinterpret_cast<const float2*>(&p.C[rb + n]);
                    v0 += o.x; v1 += o.y;
                }
                if (p.flags & F_RELU) { v0 = fmaxf(v0, 0.f); v1 = fmaxf(v1, 0.f); }
                tg_epi(p, v0, v1, rb, n);
            }
        }
}

// ---- 512-thread kernel: CTA 128m x 128n x 64k, 16 warps 4m x 4n -------------
__global__ __launch_bounds__(512) void tgemm512_k(TP p) {
    constexpr int STAGE = 65536;
    extern __shared__ char sm_raw[];
    const uint32_t smb = s2u(sm_raw);
    const int tid = threadIdx.x;
    const int lane = tid & 31;
    const int warp_m = (tid >> 5) >> 2;
    const int warp_n = (tid >> 5) & 3;

    const int m0 = blockIdx.y * 128;
    const long long n0 = (long long)blockIdx.x * 128;
    const int zc = blockIdx.z / p.Hdiv, zh = blockIdx.z % p.Hdiv;
    const long long xzb = (long long)zc * p.xz_c + (long long)zh * p.xz_h;

    auto load_chunk = [&](int c, int b) {
        const uint32_t base = smb + b * STAGE;
        const int kc = c * 64;
#pragma unroll
        for (int i = 0; i < 4; i++) {
            int idx = tid + i * 512;
            int half = idx >> 10, r = idx & 1023;
            int m = r >> 3, k16 = r & 7;
            int gm = m0 + m, gk = kc + k16 * 8;
            uint32_t dst = base + half * 16384 + SW128(m * 128 + k16 * 16);
            if (gm < p.M && gk < p.Kp)
                CP16(dst, (half ? p.Al : p.Ah) + (long long)gm * p.Kp + gk);
            else zsts16(dst);
        }
#pragma unroll
        for (int i = 0; i < 4; i++) {
            int idx = tid + i * 512;
            int half = idx >> 10, r = idx & 1023;
            int nblk = r >> 9, k = (r >> 3) & 63, n16 = r & 7;
            int gk = kc + k;
            uint32_t dst = base + 32768 + half * 16384 + nblk * 8192 + SW128(k * 128 + n16 * 16);
            if (gk < p.K) {
                long long ro = (long long)(gk / p.KH) * p.s_i + (long long)(gk % p.KH) * p.s_dh;
                CP16(dst, (half ? p.Xl : p.Xh) + xzb + ro + n0 + nblk * 64 + n16 * 8);
            } else zsts16(dst);
        }
        asm volatile("cp.async.commit_group;" ::: "memory");
    };

    float acc[2][4][4];
#pragma unroll
    for (int a = 0; a < 2; a++)
#pragma unroll
        for (int b = 0; b < 4; b++)
#pragma unroll
            for (int r = 0; r < 4; r++) acc[a][b][r] = 0.f;

    load_chunk(0, 0);

    const int a_row = warp_m * 32 + (lane & 15);
    const int a_kb  = (lane >> 4) * 16;
    const int b_grp = lane >> 3, b_lr = lane & 7;
    const int b_k0  = (b_grp & 1) * 8 + b_lr;
    const int b_n   = warp_n * 32 + (b_grp >> 1) * 8;
    const int b_nblk = b_n >> 6, b_nin = b_n & 63;

    for (int c = 0; c < p.NC; c++) {
        if (c + 1 < p.NC) {
            load_chunk(c + 1, (c + 1) & 1);
            asm volatile("cp.async.wait_group 1;" ::: "memory");
        } else {
            asm volatile("cp.async.wait_group 0;" ::: "memory");
        }
        __syncthreads();
        const uint32_t base = smb + (c & 1) * STAGE;
#pragma unroll
        for (int s = 0; s < 4; s++) {
            uint32_t af[2][2][4];
            uint32_t bf[2][2][4];
#pragma unroll
            for (int h = 0; h < 2; h++)
#pragma unroll
                for (int mi = 0; mi < 2; mi++) {
                    uint32_t ad = base + h * 16384
                        + SW128((a_row + mi * 16) * 128 + s * 32 + a_kb);
                    LDMX4(af[h][mi], ad);
                }
#pragma unroll
            for (int h = 0; h < 2; h++)
#pragma unroll
                for (int nj = 0; nj < 2; nj++) {
                    uint32_t ad = base + 32768 + h * 16384 + b_nblk * 8192
                        + SW128((s * 16 + b_k0) * 128 + (b_nin + nj * 16) * 2);
                    LDMX4T(bf[h][nj], ad);
                }
#pragma unroll
            for (int mi = 0; mi < 2; mi++)
#pragma unroll
                for (int n8 = 0; n8 < 4; n8++) {
                    int nj = n8 >> 1, pr = (n8 & 1) * 2;
                    MMA16816(acc[mi][n8], af[0][mi], bf[0][nj][pr], bf[0][nj][pr + 1]);
                    MMA16816(acc[mi][n8], af[0][mi], bf[1][nj][pr], bf[1][nj][pr + 1]);
                    MMA16816(acc[mi][n8], af[1][mi], bf[0][nj][pr], bf[0][nj][pr + 1]);
                }
        }
        __syncthreads();
    }

    const int g = lane >> 2, t4i = lane & 3;
    const long long czb = (long long)zc * p.cz_c + (long long)zh * p.cz_h + n0;
#pragma unroll
    for (int mi = 0; mi < 2; mi++)
#pragma unroll
        for (int part = 0; part < 2; part++) {
            int gm = m0 + warp_m * 32 + mi * 16 + g + part * 8;
            if (gm >= p.M) continue;
            float bs = p.bias[gm];
            long long rb = czb + (long long)gm * p.c_ld;
#pragma unroll
            for (int n8 = 0; n8 < 4; n8++) {
                int n = warp_n * 32 + n8 * 8 + t4i * 2;
                float v0 = acc[mi][n8][part * 2] + bs;
                float v1 = acc[mi][n8][part * 2 + 1] + bs;
                if (p.flags & F_ACC) {
                    float2 o = *reinterpret_cast<const float2*>(&p.C[rb + n]);
                    v0 += o.x; v1 += o.y;
                }
                if (p.flags & F_RELU) { v0 = fmaxf(v0, 0.f); v1 = fmaxf(v1, 0.f); }
                tg_epi(p, v0, v1, rb, n);
            }
        }
}

// batched weight conversion
struct CvtJob { const float* src; __nv_bfloat16 *h, *l; int M, K, Kp; };
struct CvtBatch { CvtJob j[13]; };
__global__ void cvtall_k(CvtBatch b) {
    CvtJob jb = b.j[blockIdx.y];
    int i = blockIdx.x * 256 + threadIdx.x;
    if (i >= jb.M * jb.K) return;
    int m = i / jb.K, k = i % jb.K;
    float v = jb.src[i];
    __nv_bfloat16 hv = __float2bfloat16(v);
    jb.h[m * jb.Kp + k] = hv;
    jb.l[m * jb.Kp + k] = __float2bfloat16(v - __bfloat162float(hv));
}

struct GP {
    const float* __restrict__ A;
    const float* __restrict__ X;
    const float* __restrict__ bias;
    float* C;
    __nv_bfloat16 *Ch, *Cl;
    int M, K, KH, Hdiv, relu, accum, hl;
    long long s_i, s_dh, xz_c, xz_h, cz_c, cz_h, c_ld;
};

template<int BM, int TM>
__global__ __launch_bounds__(256) void gemm_k(GP p) {
    constexpr int BK = 16, BN = 128;
    __shared__ float As[BK][BM + 1];
    __shared__ float Xs[BK][BN];
    const int tid = threadIdx.x, cn = tid & 15, cm = tid >> 4;
    const int zc = blockIdx.z / p.Hdiv, zh = blockIdx.z % p.Hdiv;
    const float* Xb = p.X + (long long)zc * p.xz_c + (long long)zh * p.xz_h + (long long)blockIdx.x * BN;
    const long long czb = (long long)zc * p.cz_c + (long long)zh * p.cz_h + (long long)blockIdx.x * BN;
    const int m0 = blockIdx.y * BM;
    float r[TM][8];
#pragma unroll
    for (int i = 0; i < TM; i++)
#pragma unroll
        for (int j = 0; j < 8; j++) r[i][j] = 0.f;
    for (int kc = 0; kc < p.K; kc += BK) {
#pragma unroll
        for (int i = 0; i < BM * BK / 256; i++) {
            int idx = tid + i * 256, am = idx >> 4, ak = idx & 15;
            int gm = m0 + am, gk = kc + ak;
            float v = 0.f;
            if (gm < p.M && gk < p.K) v = p.A[(long long)gm * p.K + gk];
            As[ak][am] = v;
        }
#pragma unroll
        for (int i = 0; i < 2; i++) {
            int idx = tid + i * 256, xk = idx >> 5, xn = (idx & 31) << 2;
            int gk = kc + xk;
            float4 v = make_float4(0.f, 0.f, 0.f, 0.f);
            if (gk < p.K) {
                long long ro = (long long)(gk / p.KH) * p.s_i + (long long)(gk % p.KH) * p.s_dh;
                v = *reinterpret_cast<const float4*>(Xb + ro + xn);
            }
            *reinterpret_cast<float4*>(&Xs[xk][xn]) = v;
        }
        __syncthreads();
#pragma unroll
        for (int kk = 0; kk < BK; kk++) {
            float4 x0 = *reinterpret_cast<const float4*>(&Xs[kk][cn * 4]);
            float4 x1 = *reinterpret_cast<const float4*>(&Xs[kk][64 + cn * 4]);
            float a[TM];
#pragma unroll
            for (int i = 0; i < TM; i++) a[i] = As[kk][cm * TM + i];
#pragma unroll
            for (int i = 0; i < TM; i++) {
                r[i][0] = fmaf(a[i], x0.x, r[i][0]); r[i][1] = fmaf(a[i], x0.y, r[i][1]);
                r[i][2] = fmaf(a[i], x0.z, r[i][2]); r[i][3] = fmaf(a[i], x0.w, r[i][3]);
                r[i][4] = fmaf(a[i], x1.x, r[i][4]); r[i][5] = fmaf(a[i], x1.y, r[i][5]);
                r[i][6] = fmaf(a[i], x1.z, r[i][6]); r[i][7] = fmaf(a[i], x1.w, r[i][7]);
            }
        }
        __syncthreads();
    }
#pragma unroll
    for (int i = 0; i < TM; i++) {
        int gm = m0 + cm * TM + i;
        if (gm >= p.M) continue;
        float bs = p.bias[gm];
        long long rb = czb + (long long)gm * p.c_ld;
#pragma unroll
        for (int h = 0; h < 2; h++) {
            int n = h * 64 + cn * 4;
            float v[4] = { r[i][h * 4] + bs, r[i][h * 4 + 1] + bs,
                           r[i][h * 4 + 2] + bs, r[i][h * 4 + 3] + bs };
            if (p.accum) {
                float4 o = *reinterpret_cast<const float4*>(&p.C[rb + n]);
                v[0] += o.x; v[1] += o.y; v[2] += o.z; v[3] += o.w;
            }
            if (p.relu)
#pragma unroll
                for (int j = 0; j < 4; j++) v[j] = fmaxf(v[j], 0.f);
            *reinterpret_cast<float4*>(&p.C[rb + n]) = make_float4(v[0], v[1], v[2], v[3]);
            if (p.hl) {
#pragma unroll
                for (int j = 0; j < 4; j += 2) {
                    __nv_bfloat16 h0 = __float2bfloat16(v[j]), h1 = __float2bfloat16(v[j + 1]);
                    __nv_bfloat162 hh; hh.x = h0; hh.y = h1;
                    __nv_bfloat162 ll;
                    ll.x = __float2bfloat16(v[j] - __bfloat162float(h0));
                    ll.y = __float2bfloat16(v[j + 1] - __bfloat162float(h1));
                    *reinterpret_cast<__nv_bfloat162*>(&p.Ch[rb + n + j]) = hh;
                    *reinterpret_cast<__nv_bfloat162*>(&p.Cl[rb + n + j]) = ll;
                }
            }
        }
    }
}

__global__ void transpose_k(const float* __restrict__ in, float* __restrict__ out,
                            __nv_bfloat16* outh, __nv_bfloat16* outl, int R, int Cc) {
    __shared__ float t[32][33];
    int c0 = blockIdx.x * 32, r0 = blockIdx.y * 32;
    int c = c0 + threadIdx.x;
#pragma unroll
    for (int i = 0; i < 32; i += 8) {
        int rr = r0 + threadIdx.y + i;
        if (rr < R && c < Cc) t[threadIdx.y + i][threadIdx.x] = in[(long long)rr * Cc + c];
    }
    __syncthreads();
    int oc = r0 + threadIdx.x;
#pragma unroll
    for (int i = 0; i < 32; i += 8) {
        int orr = c0 + threadIdx.y + i;
        if (orr < Cc && oc < R) {
            float v = t[threadIdx.x][threadIdx.y + i];
            long long a = (long long)orr * R + oc;
            out[a] = v;
            if (outh) {
                __nv_bfloat16 hv = __float2bfloat16(v);
                outh[a] = hv;
                outl[a] = __float2bfloat16(v - __bfloat162float(hv));
            }
        }
    }
}

static void run_gemm(const float* A, const float* X, const float* bias, float* C,
                     __nv_bfloat16* Ch, __nv_bfloat16* Cl,
                     int M, int N, int K, int KH, int Z, int Hdiv,
                     long long s_i, long long s_dh, long long xz_c, long long xz_h,
                     long long cz_c, long long cz_h, long long c_ld, int relu, int accum) {
    GP p;
    p.A = A; p.X = X; p.bias = bias; p.C = C; p.Ch = Ch; p.Cl = Cl;
    p.M = M; p.K = K; p.KH = KH; p.Hdiv = Hdiv;
    p.s_i = s_i; p.s_dh = s_dh; p.xz_c = xz_c; p.xz_h = xz_h;
    p.cz_c = cz_c; p.cz_h = cz_h; p.c_ld = c_ld;
    p.relu = relu; p.accum = accum; p.hl = (Ch != nullptr);
    dim3 g(N / 128, (M + 15) / 16, Z);
    gemm_k<16, 1><<<g, 256>>>(p);
}

// mi: 1/2/3 -> 512-thread 2mx8n (n-tile 256); 8 -> 512-thread 4mx4n (n-tile 128)
static void run_tg(int mi, const __nv_bfloat16* Ah, const __nv_bfloat16* Al,
                   const __nv_bfloat16* Xh, const __nv_bfloat16* Xl,
                   const float* bias, float* C, __nv_bfloat16* Ch, __nv_bfloat16* Cl,
                   int M, int Nsl, int K, int Kp, int KH, int Z, int Hdiv,
                   long long s_i, long long s_dh, long long xz_c, long long xz_h,
                   long long cz_c, long long cz_h, long long c_ld, int flags,
                   const float* Y = nullptr, const float* osc = nullptr,
                   const float* bias2 = nullptr) {
    TP p;
    p.Ah = Ah; p.Al = Al; p.Xh = Xh; p.Xl = Xl; p.bias = bias;
    p.C = C; p.Ch = Ch; p.Cl = Cl;
    p.Y = Y; p.osc = osc; p.bias2 = bias2;
    p.M = M; p.K = K; p.Kp = Kp; p.KH = KH; p.Hdiv = Hdiv;
    p.NC = (Kp + 63) / 64; p.flags = flags;
    p.s_i = s_i; p.s_dh = s_dh; p.xz_c = xz_c; p.xz_h = xz_h;
    p.cz_c = cz_c; p.cz_h = cz_h; p.c_ld = c_ld;
    if (mi == 8) {
        dim3 g(Nsl / 128, (M + 127) / 128, Z);
        tgemm512_k<<<g, 512, 131072>>>(p);
    } else if (mi == 3) {
        dim3 g(Nsl / 256, (M + 95) / 96, Z);
        tg512n_k<3><<<g, 512, 180224>>>(p);
    } else if (mi == 2) {
        dim3 g(Nsl / 256, (M + 63) / 64, Z);
        tg512n_k<2><<<g, 512, 163840>>>(p);
    } else {
        dim3 g(Nsl / 256, (M + 31) / 32, Z);
        tg512n_k<1><<<g, 512, 147456>>>(p);
    }
}

extern "C" void kernel_launch(void* const* d_in, const int* in_sizes, int n_in,
                              void* d_out, int out_size) {
    const float* x   = (const float*)d_in[0];
    const float* W0a = (const float*)d_in[1];  const float* b0a = (const float*)d_in[2];
    const float* Wl0 = (const float*)d_in[3];  const float* bl0 = (const float*)d_in[4];
    const float* W0b = (const float*)d_in[5];  const float* b0b = (const float*)d_in[6];
    const float* Wr0 = (const float*)d_in[7];  const float* br0 = (const float*)d_in[8];
    const float* W0c = (const float*)d_in[9];  const float* b0c = (const float*)d_in[10];
    const float* W1  = (const float*)d_in[11]; const float* b1  = (const float*)d_in[12];
    const float* Wl1 = (const float*)d_in[13]; const float* bl1 = (const float*)d_in[14];
    const float* W2  = (const float*)d_in[15]; const float* b2  = (const float*)d_in[16];
    const float* Wra = (const float*)d_in[17]; const float* bra = (const float*)d_in[18];
    const float* Wa  = (const float*)d_in[19]; const float* ba  = (const float*)d_in[20];
    const float* W3  = (const float*)d_in[21]; const float* b3  = (const float*)d_in[22];
    const float* Wl2 = (const float*)d_in[23]; const float* bl2 = (const float*)d_in[24];
    const float* W4  = (const float*)d_in[25]; const float* b4  = (const float*)d_in[26];
    const float* Wrb = (const float*)d_in[27]; const float* brb = (const float*)d_in[28];
    const float* Wb  = (const float*)d_in[29]; const float* bb  = (const float*)d_in[30];
    float* out = (float*)d_out;

    cudaFuncSetAttribute(tgemm512_k, cudaFuncAttributeMaxDynamicSharedMemorySize, 131072);
    cudaFuncSetAttribute(tg512n_k<3>, cudaFuncAttributeMaxDynamicSharedMemorySize, 180224);
    cudaFuncSetAttribute(tg512n_k<2>, cudaFuncAttributeMaxDynamicSharedMemorySize, 163840);
    cudaFuncSetAttribute(tg512n_k<1>, cudaFuncAttributeMaxDynamicSharedMemorySize, 147456);

    float *bx, *t0, *t2, *x2, *t9;
    cudaGetSymbolAddress((void**)&bx, g_bx);  cudaGetSymbolAddress((void**)&t0, g_b0);
    cudaGetSymbolAddress((void**)&t2, g_b2);  cudaGetSymbolAddress((void**)&x2, g_x2);
    cudaGetSymbolAddress((void**)&t9, g_b9);
    __nv_bfloat16 *bxh, *bxl, *t0h, *t0l, *t1h, *t1l, *x1h, *x1l, *t3h, *t3l, *t4h, *t4l;
    __nv_bfloat16 *t5h, *t5l, *x2h, *x2l, *t6h, *t6l, *t7h, *t7l, *t8h, *t8l;
    cudaGetSymbolAddress((void**)&bxh, g_bxh); cudaGetSymbolAddress((void**)&bxl, g_bxl);
    cudaGetSymbolAddress((void**)&t0h, g_t0h); cudaGetSymbolAddress((void**)&t0l, g_t0l);
    cudaGetSymbolAddress((void**)&t1h, g_t1h); cudaGetSymbolAddress((void**)&t1l, g_t1l);
    cudaGetSymbolAddress((void**)&x1h, g_x1h); cudaGetSymbolAddress((void**)&x1l, g_x1l);
    cudaGetSymbolAddress((void**)&t3h, g_t3h); cudaGetSymbolAddress((void**)&t3l, g_t3l);
    cudaGetSymbolAddress((void**)&t4h, g_t4h); cudaGetSymbolAddress((void**)&t4l, g_t4l);
    cudaGetSymbolAddress((void**)&t5h, g_t5h); cudaGetSymbolAddress((void**)&t5l, g_t5l);
    cudaGetSymbolAddress((void**)&x2h, g_x2h); cudaGetSymbolAddress((void**)&x2l, g_x2l);
    cudaGetSymbolAddress((void**)&t6h, g_t6h); cudaGetSymbolAddress((void**)&t6l, g_t6l);
    cudaGetSymbolAddress((void**)&t7h, g_t7h); cudaGetSymbolAddress((void**)&t7l, g_t7l);
    cudaGetSymbolAddress((void**)&t8h, g_t8h); cudaGetSymbolAddress((void**)&t8l, g_t8l);
    __nv_bfloat16 *w1h, *w1l, *w2h, *w2l, *w3h, *w3l, *w4h, *w4l, *wbh, *wbl;
    __nv_bfloat16 *wl0h, *wl0l, *wr0h, *wr0l, *w0bh, *w0bl;
    __nv_bfloat16 *wl1h, *wl1l, *wrah, *wral, *wah, *wal, *wl2h, *wl2l, *wrbh, *wrbl;
    cudaGetSymbolAddress((void**)&w1h, g_w1h);   cudaGetSymbolAddress((void**)&w1l, g_w1l);
    cudaGetSymbolAddress((void**)&w2h, g_w2h);   cudaGetSymbolAddress((void**)&w2l, g_w2l);
    cudaGetSymbolAddress((void**)&w3h, g_w3h);   cudaGetSymbolAddress((void**)&w3l, g_w3l);
    cudaGetSymbolAddress((void**)&w4h, g_w4h);   cudaGetSymbolAddress((void**)&w4l, g_w4l);
    cudaGetSymbolAddress((void**)&wbh, g_wbh);   cudaGetSymbolAddress((void**)&wbl, g_wbl);
    cudaGetSymbolAddress((void**)&wl0h, g_wl0h); cudaGetSymbolAddress((void**)&wl0l, g_wl0l);
    cudaGetSymbolAddress((void**)&wr0h, g_wr0h); cudaGetSymbolAddress((void**)&wr0l, g_wr0l);
    cudaGetSymbolAddress((void**)&w0bh, g_w0bh); cudaGetSymbolAddress((void**)&w0bl, g_w0bl);
    cudaGetSymbolAddress((void**)&wl1h, g_wl1h); cudaGetSymbolAddress((void**)&wl1l, g_wl1l);
    cudaGetSymbolAddress((void**)&wrah, g_wrah); cudaGetSymbolAddress((void**)&wral, g_wral);
    cudaGetSymbolAddress((void**)&wah, g_wah);   cudaGetSymbolAddress((void**)&wal, g_wal);
    cudaGetSymbolAddress((void**)&wl2h, g_wl2h); cudaGetSymbolAddress((void**)&wl2l, g_wl2l);
    cudaGetSymbolAddress((void**)&wrbh, g_wrbh); cudaGetSymbolAddress((void**)&wrbl, g_wrbl);

    // launch 1: input transpose
    { dim3 g((635 + 31) / 32, 32), b(32, 8);
      transpose_k<<<g, b>>>(x, bx + 130048, bxh + 130048, bxl + 130048, NB, 635); }
    // launch 2: all weight conversions
    {
        CvtBatch cb;
        cb.j[0]  = { W1,  w1h,  w1l,  75, 75, 80 };
        cb.j[1]  = { W2,  w2h,  w2l,  150, 225, 240 };
        cb.j[2]  = { W3,  w3h,  w3l,  300, 300, 304 };
        cb.j[3]  = { W4,  w4h,  w4l,  512, 600, 608 };
        cb.j[4]  = { Wb,  wbh,  wbl,  512, 450, 464 };
        cb.j[5]  = { Wl0, wl0h, wl0l, 81, 127, 128 };
        cb.j[6]  = { Wr0, wr0h, wr0l, 81, 127, 128 };
        cb.j[7]  = { W0b, w0bh, w0bl, 25, 15, 16 };
        cb.j[8]  = { Wl1, wl1h, wl1l, 41, 81, 96 };
        cb.j[9]  = { Wra, wrah, wral, 41, 81, 96 };
        cb.j[10] = { Wa,  wah,  wal,  150, 25, 32 };
        cb.j[11] = { Wl2, wl2h, wl2l, 18, 41, 48 };
        cb.j[12] = { Wrb, wrbh, wrbl, 18, 41, 48 };
        dim3 g(1200, 13);
        cvtall_k<<<g, 256>>>(cb);
    }
    // launch 3: conv0a (fp32) -> t0 + h/l
    run_gemm(W0a, bx, b0a, t0, t0h, t0l, 5, 130048, 3, 3, 5, 5,
             910336, 130048, 0, 130048, 0, 130048, 650240, 0, 0);
    // launch 4 (PROFILED): Wl0 (tensor MI=3, relu) -> t1 h/l
    run_tg(3, wl0h, wl0l, t0h, t0l, bl0, nullptr, t1h + 82944, t1l + 82944,
           81, NB, 127, 128, 1, 25, 5, 1024, 0, 650240, 130048,
           580608, 82944, 1024, F_HL | F_RELU);
    // launch 5: Wr0 (tensor MI=3) -> t2 fp32
    run_tg(3, wr0h, wr0l, bxh + 130048, bxl + 130048, br0, t2, nullptr, nullptr,
           81, NB, 127, 128, 1, 5, 5, 1024, 0, 0, 130048,
           0, 82944, 1024, F_F32);
    // launch 6: W0b (tensor MI=1) + fused W0c outer-product -> x1 h/l
    run_tg(1, w0bh, w0bl, t1h, t1l, b0b, nullptr, x1h + 82944, x1l + 82944,
           25, 82944, 15, 16, 3, 5, 5, 580608, 82944, 0, 82944,
           0, 82944, 580608, F_OUT | F_HL, t2, W0c, b0c);
    // W1 (tensor MI=3) -> t3 h/l
    run_tg(3, w1h, w1l, x1h, x1l, b1, nullptr, t3h, t3l,
           75, 82944, 75, 80, 3, 5, 5, 580608, 82944, 0, 82944,
           0, 82944, 414720, F_HL);
    // Wl1 (tensor MI=2, relu) -> t4 h/l
    run_tg(2, wl1h, wl1l, t3h, t3l, bl1, nullptr, t4h + 41984, t4l + 41984,
           41, NB, 81, 96, 1, 375, 5, 1024, 0, 414720, 82944,
           293888, 41984, 1024, F_HL | F_RELU);
    // Wra (tensor MI=2) -> t5 h/l
    run_tg(2, wrah, wral, x1h + 82944, x1l + 82944, bra, nullptr, t5h, t5l,
           41, NB, 81, 96, 1, 125, 5, 1024, 0, 580608, 82944,
           209920, 41984, 1024, F_HL);
    // Wa (tensor MI=3, 1x1) -> x2 fp32
    run_tg(3, wah, wal, t5h, t5l, ba, x2, nullptr, nullptr,
           150, 41984, 25, 32, 1, 5, 5, 209920, 0, 0, 41984,
           0, 41984, 209920, F_F32);
    // W2 (tensor MI=3, ACC) -> x2 h/l
    run_tg(3, w2h, w2l, t4h, t4l, b2, x2, x2h, x2l,
           150, 41984, 225, 240, 3, 5, 5, 293888, 41984, 0, 41984,
           0, 41984, 209920, F_ACC | F_HL);
    // W3 (tensor 4mx4n) -> t6 h/l
    run_tg(8, w3h, w3l, x2h, x2l, b3, nullptr, t6h, t6l,
           300, 41984, 300, 304, 2, 4, 4, 209920, 41984, 0, 41984,
           0, 41984, 167936, F_HL);
    // Wl2 (tensor MI=1, relu) -> t7 h/l
    run_tg(1, wl2h, wl2l, t6h, t6l, bl2, nullptr, t7h, t7l,
           18, NB, 41, 48, 1, 1200, 4, 1024, 0, 167936, 41984,
           73728, 18432, 1024, F_HL | F_RELU);
    // Wrb (tensor MI=1) -> t8 h/l
    run_tg(1, wrbh, wrbl, x2h, x2l, brb, nullptr, t8h, t8l,
           18, NB, 41, 48, 1, 750, 5, 1024, 0, 209920, 41984,
           92160, 18432, 1024, F_HL);
    // Wb (tensor 4mx4n) -> t9 fp32
    run_tg(8, wbh, wbl, t8h, t8l, bb, t9, nullptr, nullptr,
           512, 18432, 450, 464, 3, 3, 3, 92160, 18432, 0, 18432,
           0, 18432, 55296, F_F32);
    // W4 (tensor 4mx4n, ACC) -> t9 fp32
    run_tg(8, w4h, w4l, t7h, t7l, b4, t9, nullptr, nullptr,
           512, 18432, 600, 608, 2, 3, 3, 73728, 18432, 0, 18432,
           0, 18432, 55296, F_F32 | F_ACC);
    // final transpose
    { dim3 g(32, (27648 + 31) / 32), b(32, 8);
      transpose_k<<<g, b>>>(t9, out, nullptr, nullptr, 27648, NB); }
    (void)in_sizes; (void)n_in; (void)out_size;
}

// round 13
// speedup vs baseline: 1.0572x; 1.0572x over previous
#include <cuda_runtime.h>
#include <cuda_bf16.h>
#include <cstdint>

#define NB 1024

// fp32 buffers (zero-init device globals; pad rows never written)
__device__ float g_bx[7 * 130048];
__device__ float g_b0[5 * 650240];   // t0 conv0a out
__device__ float g_b2[5 * 82944];    // t2 Wr0 out
__device__ float g_x2[150 * 209920]; // x2 (Wa out, acc target)
__device__ float g_b9[512 * 55296];  // final pre-transpose

// bf16 hi/lo activations
__device__ __align__(16) __nv_bfloat16 g_bxh[7 * 130048],  g_bxl[7 * 130048];
__device__ __align__(16) __nv_bfloat16 g_t0h[5 * 650240],  g_t0l[5 * 650240];
__device__ __align__(16) __nv_bfloat16 g_t1h[5 * 580608],  g_t1l[5 * 580608];
__device__ __align__(16) __nv_bfloat16 g_x1h[25 * 580608], g_x1l[25 * 580608];
__device__ __align__(16) __nv_bfloat16 g_t3h[75 * 414720], g_t3l[75 * 414720];
__device__ __align__(16) __nv_bfloat16 g_t4h[75 * 293888], g_t4l[75 * 293888];
__device__ __align__(16) __nv_bfloat16 g_t5h[25 * 209920], g_t5l[25 * 209920];
__device__ __align__(16) __nv_bfloat16 g_x2h[150 * 209920], g_x2l[150 * 209920];
__device__ __align__(16) __nv_bfloat16 g_t6h[300 * 167936], g_t6l[300 * 167936];
__device__ __align__(16) __nv_bfloat16 g_t7h[300 * 73728], g_t7l[300 * 73728];
__device__ __align__(16) __nv_bfloat16 g_t8h[150 * 92160], g_t8l[150 * 92160];
// bf16 hi/lo weights (K padded to mult 16)
__device__ __align__(16) __nv_bfloat16 g_w1h[75 * 80],    g_w1l[75 * 80];
__device__ __align__(16) __nv_bfloat16 g_w2h[150 * 240],  g_w2l[150 * 240];
__device__ __align__(16) __nv_bfloat16 g_w3h[300 * 304],  g_w3l[300 * 304];
__device__ __align__(16) __nv_bfloat16 g_w4h[512 * 608],  g_w4l[512 * 608];
__device__ __align__(16) __nv_bfloat16 g_wbh[512 * 464],  g_wbl[512 * 464];
__device__ __align__(16) __nv_bfloat16 g_wl0h[81 * 128],  g_wl0l[81 * 128];
__device__ __align__(16) __nv_bfloat16 g_wr0h[81 * 128],  g_wr0l[81 * 128];
__device__ __align__(16) __nv_bfloat16 g_w0bh[25 * 16],   g_w0bl[25 * 16];
__device__ __align__(16) __nv_bfloat16 g_wl1h[41 * 96],   g_wl1l[41 * 96];
__device__ __align__(16) __nv_bfloat16 g_wrah[41 * 96],   g_wral[41 * 96];
__device__ __align__(16) __nv_bfloat16 g_wah[150 * 32],   g_wal[150 * 32];
__device__ __align__(16) __nv_bfloat16 g_wl2h[18 * 48],   g_wl2l[18 * 48];
__device__ __align__(16) __nv_bfloat16 g_wrbh[18 * 48],   g_wrbl[18 * 48];

__device__ __forceinline__ uint32_t s2u(const void* p) {
    uint32_t a;
    asm("{ .reg .u64 t; cvta.to.shared.u64 t, %1; cvt.u32.u64 %0, t; }" : "=r"(a) : "l"(p));
    return a;
}
#define SW128(o) ((o) ^ (((o) >> 3) & 0x70))
#define CP16(d, s) asm volatile("cp.async.cg.shared.global [%0], [%1], 16;" :: "r"(d), "l"(s))
__device__ __forceinline__ void zsts16(uint32_t d) {
    asm volatile("st.shared.v4.b32 [%0], {%1,%1,%1,%1};" :: "r"(d), "r"(0u));
}
#define LDMX4(r, a) \
    asm volatile("ldmatrix.sync.aligned.m8n8.x4.shared.b16 {%0,%1,%2,%3}, [%4];" \
        : "=r"((r)[0]), "=r"((r)[1]), "=r"((r)[2]), "=r"((r)[3]) : "r"(a))
#define LDMX4T(r, a) \
    asm volatile("ldmatrix.sync.aligned.m8n8.x4.trans.shared.b16 {%0,%1,%2,%3}, [%4];" \
        : "=r"((r)[0]), "=r"((r)[1]), "=r"((r)[2]), "=r"((r)[3]) : "r"(a))
#define MMA16816(c, a, b0, b1) \
    asm volatile("mma.sync.aligned.m16n8k16.row.col.f32.bf16.bf16.f32 " \
        "{%0,%1,%2,%3},{%4,%5,%6,%7},{%8,%9},{%0,%1,%2,%3};" \
        : "+f"((c)[0]), "+f"((c)[1]), "+f"((c)[2]), "+f"((c)[3]) \
        : "r"((a)[0]), "r"((a)[1]), "r"((a)[2]), "r"((a)[3]), "r"(b0), "r"(b1))

#define F_ACC  1
#define F_RELU 2
#define F_F32  4
#define F_HL   8
#define F_OUT  16

struct TP {
    const __nv_bfloat16 *Ah, *Al, *Xh, *Xl;
    const float* bias;
    float* C;
    __nv_bfloat16 *Ch, *Cl;
    const float* Y;
    const float* osc;
    const float* bias2;
    int M, K, Kp, KH, Hdiv, NC, flags;
    long long s_i, s_dh, xz_c, xz_h, cz_c, cz_h, c_ld;
};

__device__ __forceinline__ void tg_epi(const TP& p, float v0, float v1,
                                       long long rb, int n) {
    if (p.flags & F_F32)
        *reinterpret_cast<float2*>(&p.C[rb + n]) = make_float2(v0, v1);
    if (p.flags & F_HL) {
        __nv_bfloat16 h0 = __float2bfloat16(v0), h1 = __float2bfloat16(v1);
        __nv_bfloat162 hh; hh.x = h0; hh.y = h1;
        __nv_bfloat162 ll;
        ll.x = __float2bfloat16(v0 - __bfloat162float(h0));
        ll.y = __float2bfloat16(v1 - __bfloat162float(h1));
        *reinterpret_cast<__nv_bfloat162*>(&p.Ch[rb + n]) = hh;
        *reinterpret_cast<__nv_bfloat162*>(&p.Cl[rb + n]) = ll;
    }
}

// --- 256-thread kernel: CTA (32*MI)m x 128n x 64k, 8 warps 2mx4n, 2 CTAs/SM --
template<int MI>
__global__ __launch_bounds__(256, 2) void tgemm_k(TP p) {
    constexpr int A_HALF = MI * 4096;
    constexpr int XOFF = 2 * A_HALF;
    constexpr int STAGE = XOFF + 32768;
    extern __shared__ char sm_raw[];
    const uint32_t smb = s2u(sm_raw);
    const int tid = threadIdx.x;
    const int lane = tid & 31;
    const int warp_m = (tid >> 5) >> 2;
    const int warp_n = (tid >> 5) & 3;

    const int m0 = blockIdx.y * (MI * 32);
    const long long n0 = (long long)blockIdx.x * 128;
    const int zc = blockIdx.z / p.Hdiv, zh = blockIdx.z % p.Hdiv;
    const long long xzb = (long long)zc * p.xz_c + (long long)zh * p.xz_h;

    auto load_chunk = [&](int c, int b) {
        const uint32_t base = smb + b * STAGE;
        const int kc = c * 64;
#pragma unroll
        for (int i = 0; i < 2 * MI; i++) {
            int idx = tid + i * 256;
            int half = idx / (MI * 256), r = idx % (MI * 256);
            int m = r >> 3, k16 = r & 7;
            int gm = m0 + m, gk = kc + k16 * 8;
            uint32_t dst = base + half * A_HALF + SW128(m * 128 + k16 * 16);
            if (gm < p.M && gk < p.Kp)
                CP16(dst, (half ? p.Al : p.Ah) + (long long)gm * p.Kp + gk);
            else zsts16(dst);
        }
#pragma unroll
        for (int i = 0; i < 8; i++) {
            int idx = tid + i * 256;
            int half = idx >> 10, r = idx & 1023;
            int nblk = r >> 9, k = (r >> 3) & 63, n16 = r & 7;
            int gk = kc + k;
            uint32_t dst = base + XOFF + half * 16384 + nblk * 8192 + SW128(k * 128 + n16 * 16);
            if (gk < p.K) {
                long long ro = (long long)(gk / p.KH) * p.s_i + (long long)(gk % p.KH) * p.s_dh;
                CP16(dst, (half ? p.Xl : p.Xh) + xzb + ro + n0 + nblk * 64 + n16 * 8);
            } else zsts16(dst);
        }
        asm volatile("cp.async.commit_group;" ::: "memory");
    };

    float acc[MI][4][4];
#pragma unroll
    for (int a = 0; a < MI; a++)
#pragma unroll
        for (int b = 0; b < 4; b++)
#pragma unroll
            for (int r = 0; r < 4; r++) acc[a][b][r] = 0.f;

    load_chunk(0, 0);

    const int a_row = warp_m * (MI * 16) + (lane & 15);
    const int a_kb  = (lane >> 4) * 16;
    const int b_grp = lane >> 3, b_lr = lane & 7;
    const int b_k0  = (b_grp & 1) * 8 + b_lr;
    const int b_n   = warp_n * 32 + (b_grp >> 1) * 8;
    const int b_nblk = b_n >> 6, b_nin = b_n & 63;

    for (int c = 0; c < p.NC; c++) {
        if (c + 1 < p.NC) {
            load_chunk(c + 1, (c + 1) & 1);
            asm volatile("cp.async.wait_group 1;" ::: "memory");
        } else {
            asm volatile("cp.async.wait_group 0;" ::: "memory");
        }
        __syncthreads();
        const uint32_t base = smb + (c & 1) * STAGE;
#pragma unroll
        for (int s = 0; s < 4; s++) {
            uint32_t af[2][MI][4];
            uint32_t bf[2][2][4];
#pragma unroll
            for (int h = 0; h < 2; h++)
#pragma unroll
                for (int mi = 0; mi < MI; mi++) {
                    uint32_t ad = base + h * A_HALF
                        + SW128((a_row + mi * 16) * 128 + s * 32 + a_kb);
                    LDMX4(af[h][mi], ad);
                }
#pragma unroll
            for (int h = 0; h < 2; h++)
#pragma unroll
                for (int nj = 0; nj < 2; nj++) {
                    uint32_t ad = base + XOFF + h * 16384 + b_nblk * 8192
                        + SW128((s * 16 + b_k0) * 128 + (b_nin + nj * 16) * 2);
                    LDMX4T(bf[h][nj], ad);
                }
#pragma unroll
            for (int mi = 0; mi < MI; mi++)
#pragma unroll
                for (int n8 = 0; n8 < 4; n8++) {
                    int nj = n8 >> 1, pr = (n8 & 1) * 2;
                    MMA16816(acc[mi][n8], af[0][mi], bf[0][nj][pr], bf[0][nj][pr + 1]);
                    MMA16816(acc[mi][n8], af[0][mi], bf[1][nj][pr], bf[1][nj][pr + 1]);
                    MMA16816(acc[mi][n8], af[1][mi], bf[0][nj][pr], bf[0][nj][pr + 1]);
                }
        }
        __syncthreads();
    }

    const int g = lane >> 2, t4i = lane & 3;
    const long long czb = (long long)zc * p.cz_c + (long long)zh * p.cz_h + n0;
#pragma unroll
    for (int mi = 0; mi < MI; mi++)
#pragma unroll
        for (int part = 0; part < 2; part++) {
            int gm = m0 + warp_m * (MI * 16) + mi * 16 + g + part * 8;
            if (gm >= p.M) continue;
            float bs = p.bias[gm];
            float ow = 0.f;
            if (p.flags & F_OUT) { bs += p.bias2[gm]; ow = p.osc[gm]; }
            long long rb = czb + (long long)gm * p.c_ld;
#pragma unroll
            for (int n8 = 0; n8 < 4; n8++) {
                int n = warp_n * 32 + n8 * 8 + t4i * 2;
                float v0 = acc[mi][n8][part * 2] + bs;
                float v1 = acc[mi][n8][part * 2 + 1] + bs;
                if (p.flags & F_OUT) {
                    float2 y = *reinterpret_cast<const float2*>(&p.Y[czb + n]);
                    v0 += ow * y.x; v1 += ow * y.y;
                }
                if (p.flags & F_ACC) {
                    float2 o = *reinterpret_cast<const float2*>(&p.C[rb + n]);
                    v0 += o.x; v1 += o.y;
                }
                if (p.flags & F_RELU) { v0 = fmaxf(v0, 0.f); v1 = fmaxf(v1, 0.f); }
                tg_epi(p, v0, v1, rb, n);
            }
        }
}

// batched weight conversion
struct CvtJob { const float* src; __nv_bfloat16 *h, *l; int M, K, Kp; };
struct CvtBatch { CvtJob j[13]; };
__global__ void cvtall_k(CvtBatch b) {
    CvtJob jb = b.j[blockIdx.y];
    int i = blockIdx.x * 256 + threadIdx.x;
    if (i >= jb.M * jb.K) return;
    int m = i / jb.K, k = i % jb.K;
    float v = jb.src[i];
    __nv_bfloat16 hv = __float2bfloat16(v);
    jb.h[m * jb.Kp + k] = hv;
    jb.l[m * jb.Kp + k] = __float2bfloat16(v - __bfloat162float(hv));
}

struct GP {
    const float* __restrict__ A;
    const float* __restrict__ X;
    const float* __restrict__ bias;
    float* C;
    __nv_bfloat16 *Ch, *Cl;
    int M, K, KH, Hdiv, relu, accum, hl;
    long long s_i, s_dh, xz_c, xz_h, cz_c, cz_h, c_ld;
};

template<int BM, int TM>
__global__ __launch_bounds__(256) void gemm_k(GP p) {
    constexpr int BK = 16, BN = 128;
    __shared__ float As[BK][BM + 1];
    __shared__ float Xs[BK][BN];
    const int tid = threadIdx.x, cn = tid & 15, cm = tid >> 4;
    const int zc = blockIdx.z / p.Hdiv, zh = blockIdx.z % p.Hdiv;
    const float* Xb = p.X + (long long)zc * p.xz_c + (long long)zh * p.xz_h + (long long)blockIdx.x * BN;
    const long long czb = (long long)zc * p.cz_c + (long long)zh * p.cz_h + (long long)blockIdx.x * BN;
    const int m0 = blockIdx.y * BM;
    float r[TM][8];
#pragma unroll
    for (int i = 0; i < TM; i++)
#pragma unroll
        for (int j = 0; j < 8; j++) r[i][j] = 0.f;
    for (int kc = 0; kc < p.K; kc += BK) {
#pragma unroll
        for (int i = 0; i < BM * BK / 256; i++) {
            int idx = tid + i * 256, am = idx >> 4, ak = idx & 15;
            int gm = m0 + am, gk = kc + ak;
            float v = 0.f;
            if (gm < p.M && gk < p.K) v = p.A[(long long)gm * p.K + gk];
            As[ak][am] = v;
        }
#pragma unroll
        for (int i = 0; i < 2; i++) {
            int idx = tid + i * 256, xk = idx >> 5, xn = (idx & 31) << 2;
            int gk = kc + xk;
            float4 v = make_float4(0.f, 0.f, 0.f, 0.f);
            if (gk < p.K) {
                long long ro = (long long)(gk / p.KH) * p.s_i + (long long)(gk % p.KH) * p.s_dh;
                v = *reinterpret_cast<const float4*>(Xb + ro + xn);
            }
            *reinterpret_cast<float4*>(&Xs[xk][xn]) = v;
        }
        __syncthreads();
#pragma unroll
        for (int kk = 0; kk < BK; kk++) {
            float4 x0 = *reinterpret_cast<const float4*>(&Xs[kk][cn * 4]);
            float4 x1 = *reinterpret_cast<const float4*>(&Xs[kk][64 + cn * 4]);
            float a[TM];
#pragma unroll
            for (int i = 0; i < TM; i++) a[i] = As[kk][cm * TM + i];
#pragma unroll
            for (int i = 0; i < TM; i++) {
                r[i][0] = fmaf(a[i], x0.x, r[i][0]); r[i][1] = fmaf(a[i], x0.y, r[i][1]);
                r[i][2] = fmaf(a[i], x0.z, r[i][2]); r[i][3] = fmaf(a[i], x0.w, r[i][3]);
                r[i][4] = fmaf(a[i], x1.x, r[i][4]); r[i][5] = fmaf(a[i], x1.y, r[i][5]);
                r[i][6] = fmaf(a[i], x1.z, r[i][6]); r[i][7] = fmaf(a[i], x1.w, r[i][7]);
            }
        }
        __syncthreads();
    }
#pragma unroll
    for (int i = 0; i < TM; i++) {
        int gm = m0 + cm * TM + i;
        if (gm >= p.M) continue;
        float bs = p.bias[gm];
        long long rb = czb + (long long)gm * p.c_ld;
#pragma unroll
        for (int h = 0; h < 2; h++) {
            int n = h * 64 + cn * 4;
            float v[4] = { r[i][h * 4] + bs, r[i][h * 4 + 1] + bs,
                           r[i][h * 4 + 2] + bs, r[i][h * 4 + 3] + bs };
            if (p.accum) {
                float4 o = *reinterpret_cast<const float4*>(&p.C[rb + n]);
                v[0] += o.x; v[1] += o.y; v[2] += o.z; v[3] += o.w;
            }
            if (p.relu)
#pragma unroll
                for (int j = 0; j < 4; j++) v[j] = fmaxf(v[j], 0.f);
            *reinterpret_cast<float4*>(&p.C[rb + n]) = make_float4(v[0], v[1], v[2], v[3]);
            if (p.hl) {
#pragma unroll
                for (int j = 0; j < 4; j += 2) {
                    __nv_bfloat16 h0 = __float2bfloat16(v[j]), h1 = __float2bfloat16(v[j + 1]);
                    __nv_bfloat162 hh; hh.x = h0; hh.y = h1;
                    __nv_bfloat162 ll;
                    ll.x = __float2bfloat16(v[j] - __bfloat162float(h0));
                    ll.y = __float2bfloat16(v[j + 1] - __bfloat162float(h1));
                    *reinterpret_cast<__nv_bfloat162*>(&p.Ch[rb + n + j]) = hh;
                    *reinterpret_cast<__nv_bfloat162*>(&p.Cl[rb + n + j]) = ll;
                }
            }
        }
    }
}

__global__ void transpose_k(const float* __restrict__ in, float* __restrict__ out,
                            __nv_bfloat16* outh, __nv_bfloat16* outl, int R, int Cc) {
    __shared__ float t[32][33];
    int c0 = blockIdx.x * 32, r0 = blockIdx.y * 32;
    int c = c0 + threadIdx.x;
#pragma unroll
    for (int i = 0; i < 32; i += 8) {
        int rr = r0 + threadIdx.y + i;
        if (rr < R && c < Cc) t[threadIdx.y + i][threadIdx.x] = in[(long long)rr * Cc + c];
    }
    __syncthreads();
    int oc = r0 + threadIdx.x;
#pragma unroll
    for (int i = 0; i < 32; i += 8) {
        int orr = c0 + threadIdx.y + i;
        if (orr < Cc && oc < R) {
            float v = t[threadIdx.x][threadIdx.y + i];
            long long a = (long long)orr * R + oc;
            out[a] = v;
            if (outh) {
                __nv_bfloat16 hv = __float2bfloat16(v);
                outh[a] = hv;
                outl[a] = __float2bfloat16(v - __bfloat162float(hv));
            }
        }
    }
}

static void run_gemm(const float* A, const float* X, const float* bias, float* C,
                     __nv_bfloat16* Ch, __nv_bfloat16* Cl,
                     int M, int N, int K, int KH, int Z, int Hdiv,
                     long long s_i, long long s_dh, long long xz_c, long long xz_h,
                     long long cz_c, long long cz_h, long long c_ld, int relu, int accum) {
    GP p;
    p.A = A; p.X = X; p.bias = bias; p.C = C; p.Ch = Ch; p.Cl = Cl;
    p.M = M; p.K = K; p.KH = KH; p.Hdiv = Hdiv;
    p.s_i = s_i; p.s_dh = s_dh; p.xz_c = xz_c; p.xz_h = xz_h;
    p.cz_c = cz_c; p.cz_h = cz_h; p.c_ld = c_ld;
    p.relu = relu; p.accum = accum; p.hl = (Ch != nullptr);
    dim3 g(N / 128, (M + 15) / 16, Z);
    gemm_k<16, 1><<<g, 256>>>(p);
}

// mi: 1 or 2; both run at 2 CTAs/SM
static void run_tg(int mi, const __nv_bfloat16* Ah, const __nv_bfloat16* Al,
                   const __nv_bfloat16* Xh, const __nv_bfloat16* Xl,
                   const float* bias, float* C, __nv_bfloat16* Ch, __nv_bfloat16* Cl,
                   int M, int Nsl, int K, int Kp, int KH, int Z, int Hdiv,
                   long long s_i, long long s_dh, long long xz_c, long long xz_h,
                   long long cz_c, long long cz_h, long long c_ld, int flags,
                   const float* Y = nullptr, const float* osc = nullptr,
                   const float* bias2 = nullptr) {
    TP p;
    p.Ah = Ah; p.Al = Al; p.Xh = Xh; p.Xl = Xl; p.bias = bias;
    p.C = C; p.Ch = Ch; p.Cl = Cl;
    p.Y = Y; p.osc = osc; p.bias2 = bias2;
    p.M = M; p.K = K; p.Kp = Kp; p.KH = KH; p.Hdiv = Hdiv;
    p.NC = (Kp + 63) / 64; p.flags = flags;
    p.s_i = s_i; p.s_dh = s_dh; p.xz_c = xz_c; p.xz_h = xz_h;
    p.cz_c = cz_c; p.cz_h = cz_h; p.c_ld = c_ld;
    if (mi == 2) {
        dim3 g(Nsl / 128, (M + 63) / 64, Z);
        tgemm_k<2><<<g, 256, 98304>>>(p);
    } else {
        dim3 g(Nsl / 128, (M + 31) / 32, Z);
        tgemm_k<1><<<g, 256, 81920>>>(p);
    }
}

extern "C" void kernel_launch(void* const* d_in, const int* in_sizes, int n_in,
                              void* d_out, int out_size) {
    const float* x   = (const float*)d_in[0];
    const float* W0a = (const float*)d_in[1];  const float* b0a = (const float*)d_in[2];
    const float* Wl0 = (const float*)d_in[3];  const float* bl0 = (const float*)d_in[4];
    const float* W0b = (const float*)d_in[5];  const float* b0b = (const float*)d_in[6];
    const float* Wr0 = (const float*)d_in[7];  const float* br0 = (const float*)d_in[8];
    const float* W0c = (const float*)d_in[9];  const float* b0c = (const float*)d_in[10];
    const float* W1  = (const float*)d_in[11]; const float* b1  = (const float*)d_in[12];
    const float* Wl1 = (const float*)d_in[13]; const float* bl1 = (const float*)d_in[14];
    const float* W2  = (const float*)d_in[15]; const float* b2  = (const float*)d_in[16];
    const float* Wra = (const float*)d_in[17]; const float* bra = (const float*)d_in[18];
    const float* Wa  = (const float*)d_in[19]; const float* ba  = (const float*)d_in[20];
    const float* W3  = (const float*)d_in[21]; const float* b3  = (const float*)d_in[22];
    const float* Wl2 = (const float*)d_in[23]; const float* bl2 = (const float*)d_in[24];
    const float* W4  = (const float*)d_in[25]; const float* b4  = (const float*)d_in[26];
    const float* Wrb = (const float*)d_in[27]; const float* brb = (const float*)d_in[28];
    const float* Wb  = (const float*)d_in[29]; const float* bb  = (const float*)d_in[30];
    float* out = (float*)d_out;

    cudaFuncSetAttribute(tgemm_k<2>, cudaFuncAttributeMaxDynamicSharedMemorySize, 98304);
    cudaFuncSetAttribute(tgemm_k<1>, cudaFuncAttributeMaxDynamicSharedMemorySize, 81920);

    float *bx, *t0, *t2, *x2, *t9;
    cudaGetSymbolAddress((void**)&bx, g_bx);  cudaGetSymbolAddress((void**)&t0, g_b0);
    cudaGetSymbolAddress((void**)&t2, g_b2);  cudaGetSymbolAddress((void**)&x2, g_x2);
    cudaGetSymbolAddress((void**)&t9, g_b9);
    __nv_bfloat16 *bxh, *bxl, *t0h, *t0l, *t1h, *t1l, *x1h, *x1l, *t3h, *t3l, *t4h, *t4l;
    __nv_bfloat16 *t5h, *t5l, *x2h, *x2l, *t6h, *t6l, *t7h, *t7l, *t8h, *t8l;
    cudaGetSymbolAddress((void**)&bxh, g_bxh); cudaGetSymbolAddress((void**)&bxl, g_bxl);
    cudaGetSymbolAddress((void**)&t0h, g_t0h); cudaGetSymbolAddress((void**)&t0l, g_t0l);
    cudaGetSymbolAddress((void**)&t1h, g_t1h); cudaGetSymbolAddress((void**)&t1l, g_t1l);
    cudaGetSymbolAddress((void**)&x1h, g_x1h); cudaGetSymbolAddress((void**)&x1l, g_x1l);
    cudaGetSymbolAddress((void**)&t3h, g_t3h); cudaGetSymbolAddress((void**)&t3l, g_t3l);
    cudaGetSymbolAddress((void**)&t4h, g_t4h); cudaGetSymbolAddress((void**)&t4l, g_t4l);
    cudaGetSymbolAddress((void**)&t5h, g_t5h); cudaGetSymbolAddress((void**)&t5l, g_t5l);
    cudaGetSymbolAddress((void**)&x2h, g_x2h); cudaGetSymbolAddress((void**)&x2l, g_x2l);
    cudaGetSymbolAddress((void**)&t6h, g_t6h); cudaGetSymbolAddress((void**)&t6l, g_t6l);
    cudaGetSymbolAddress((void**)&t7h, g_t7h); cudaGetSymbolAddress((void**)&t7l, g_t7l);
    cudaGetSymbolAddress((void**)&t8h, g_t8h); cudaGetSymbolAddress((void**)&t8l, g_t8l);
    __nv_bfloat16 *w1h, *w1l, *w2h, *w2l, *w3h, *w3l, *w4h, *w4l, *wbh, *wbl;
    __nv_bfloat16 *wl0h, *wl0l, *wr0h, *wr0l, *w0bh, *w0bl;
    __nv_bfloat16 *wl1h, *wl1l, *wrah, *wral, *wah, *wal, *wl2h, *wl2l, *wrbh, *wrbl;
    cudaGetSymbolAddress((void**)&w1h, g_w1h);   cudaGetSymbolAddress((void**)&w1l, g_w1l);
    cudaGetSymbolAddress((void**)&w2h, g_w2h);   cudaGetSymbolAddress((void**)&w2l, g_w2l);
    cudaGetSymbolAddress((void**)&w3h, g_w3h);   cudaGetSymbolAddress((void**)&w3l, g_w3l);
    cudaGetSymbolAddress((void**)&w4h, g_w4h);   cudaGetSymbolAddress((void**)&w4l, g_w4l);
    cudaGetSymbolAddress((void**)&wbh, g_wbh);   cudaGetSymbolAddress((void**)&wbl, g_wbl);
    cudaGetSymbolAddress((void**)&wl0h, g_wl0h); cudaGetSymbolAddress((void**)&wl0l, g_wl0l);
    cudaGetSymbolAddress((void**)&wr0h, g_wr0h); cudaGetSymbolAddress((void**)&wr0l, g_wr0l);
    cudaGetSymbolAddress((void**)&w0bh, g_w0bh); cudaGetSymbolAddress((void**)&w0bl, g_w0bl);
    cudaGetSymbolAddress((void**)&wl1h, g_wl1h); cudaGetSymbolAddress((void**)&wl1l, g_wl1l);
    cudaGetSymbolAddress((void**)&wrah, g_wrah); cudaGetSymbolAddress((void**)&wral, g_wral);
    cudaGetSymbolAddress((void**)&wah, g_wah);   cudaGetSymbolAddress((void**)&wal, g_wal);
    cudaGetSymbolAddress((void**)&wl2h, g_wl2h); cudaGetSymbolAddress((void**)&wl2l, g_wl2l);
    cudaGetSymbolAddress((void**)&wrbh, g_wrbh); cudaGetSymbolAddress((void**)&wrbl, g_wrbl);

    // launch 1: input transpose
    { dim3 g((635 + 31) / 32, 32), b(32, 8);
      transpose_k<<<g, b>>>(x, bx + 130048, bxh + 130048, bxl + 130048, NB, 635); }
    // launch 2: all weight conversions
    {
        CvtBatch cb;
        cb.j[0]  = { W1,  w1h,  w1l,  75, 75, 80 };
        cb.j[1]  = { W2,  w2h,  w2l,  150, 225, 240 };
        cb.j[2]  = { W3,  w3h,  w3l,  300, 300, 304 };
        cb.j[3]  = { W4,  w4h,  w4l,  512, 600, 608 };
        cb.j[4]  = { Wb,  wbh,  wbl,  512, 450, 464 };
        cb.j[5]  = { Wl0, wl0h, wl0l, 81, 127, 128 };
        cb.j[6]  = { Wr0, wr0h, wr0l, 81, 127, 128 };
        cb.j[7]  = { W0b, w0bh, w0bl, 25, 15, 16 };
        cb.j[8]  = { Wl1, wl1h, wl1l, 41, 81, 96 };
        cb.j[9]  = { Wra, wrah, wral, 41, 81, 96 };
        cb.j[10] = { Wa,  wah,  wal,  150, 25, 32 };
        cb.j[11] = { Wl2, wl2h, wl2l, 18, 41, 48 };
        cb.j[12] = { Wrb, wrbh, wrbl, 18, 41, 48 };
        dim3 g(1200, 13);
        cvtall_k<<<g, 256>>>(cb);
    }
    // launch 3: conv0a (fp32) -> t0 + h/l
    run_gemm(W0a, bx, b0a, t0, t0h, t0l, 5, 130048, 3, 3, 5, 5,
             910336, 130048, 0, 130048, 0, 130048, 650240, 0, 0);
    // launch 4 (PROFILED): Wl0 (tensor MI2, relu) -> t1 h/l
    run_tg(2, wl0h, wl0l, t0h, t0l, bl0, nullptr, t1h + 82944, t1l + 82944,
           81, NB, 127, 128, 1, 25, 5, 1024, 0, 650240, 130048,
           580608, 82944, 1024, F_HL | F_RELU);
    // launch 5: Wr0 (tensor MI2) -> t2 fp32
    run_tg(2, wr0h, wr0l, bxh + 130048, bxl + 130048, br0, t2, nullptr, nullptr,
           81, NB, 127, 128, 1, 5, 5, 1024, 0, 0, 130048,
           0, 82944, 1024, F_F32);
    // launch 6: W0b (tensor MI1) + fused W0c outer-product -> x1 h/l
    run_tg(1, w0bh, w0bl, t1h, t1l, b0b, nullptr, x1h + 82944, x1l + 82944,
           25, 82944, 15, 16, 3, 5, 5, 580608, 82944, 0, 82944,
           0, 82944, 580608, F_OUT | F_HL, t2, W0c, b0c);
    // W1 (tensor MI2) -> t3 h/l
    run_tg(2, w1h, w1l, x1h, x1l, b1, nullptr, t3h, t3l,
           75, 82944, 75, 80, 3, 5, 5, 580608, 82944, 0, 82944,
           0, 82944, 414720, F_HL);
    // Wl1 (tensor MI2, relu) -> t4 h/l
    run_tg(2, wl1h, wl1l, t3h, t3l, bl1, nullptr, t4h + 41984, t4l + 41984,
           41, NB, 81, 96, 1, 375, 5, 1024, 0, 414720, 82944,
           293888, 41984, 1024, F_HL | F_RELU);
    // Wra (tensor MI2) -> t5 h/l
    run_tg(2, wrah, wral, x1h + 82944, x1l + 82944, bra, nullptr, t5h, t5l,
           41, NB, 81, 96, 1, 125, 5, 1024, 0, 580608, 82944,
           209920, 41984, 1024, F_HL);
    // Wa (tensor MI2, 1x1) -> x2 fp32
    run_tg(2, wah, wal, t5h, t5l, ba, x2, nullptr, nullptr,
           150, 41984, 25, 32, 1, 5, 5, 209920, 0, 0, 41984,
           0, 41984, 209920, F_F32);
    // W2 (tensor MI2, ACC) -> x2 h/l
    run_tg(2, w2h, w2l, t4h, t4l, b2, x2, x2h, x2l,
           150, 41984, 225, 240, 3, 5, 5, 293888, 41984, 0, 41984,
           0, 41984, 209920, F_ACC | F_HL);
    // W3 (tensor MI2) -> t6 h/l
    run_tg(2, w3h, w3l, x2h, x2l, b3, nullptr, t6h, t6l,
           300, 41984, 300, 304, 2, 4, 4, 209920, 41984, 0, 41984,
           0, 41984, 167936, F_HL);
    // Wl2 (tensor MI1, relu) -> t7 h/l
    run_tg(1, wl2h, wl2l, t6h, t6l, bl2, nullptr, t7h, t7l,
           18, NB, 41, 48, 1, 1200, 4, 1024, 0, 167936, 41984,
           73728, 18432, 1024, F_HL | F_RELU);
    // Wrb (tensor MI1) -> t8 h/l
    run_tg(1, wrbh, wrbl, x2h, x2l, brb, nullptr, t8h, t8l,
           18, NB, 41, 48, 1, 750, 5, 1024, 0, 209920, 41984,
           92160, 18432, 1024, F_HL);
    // Wb (tensor MI2) -> t9 fp32
    run_tg(2, wbh, wbl, t8h, t8l, bb, t9, nullptr, nullptr,
           512, 18432, 450, 464, 3, 3, 3, 92160, 18432, 0, 18432,
           0, 18432, 55296, F_F32);
    // W4 (tensor MI2, ACC) -> t9 fp32
    run_tg(2, w4h, w4l, t7h, t7l, b4, t9, nullptr, nullptr,
           512, 18432, 600, 608, 2, 3, 3, 73728, 18432, 0, 18432,
           0, 18432, 55296, F_F32 | F_ACC);
    // final transpose
    { dim3 g(32, (27648 + 31) / 32), b(32, 8);
      transpose_k<<<g, b>>>(t9, out, nullptr, nullptr, 27648, NB); }
    (void)in_sizes; (void)n_in; (void)out_size;
}

// round 14
// speedup vs baseline: 1.0869x; 1.0280x over previous
#include <cuda_runtime.h>
#include <cuda_bf16.h>
#include <cstdint>

#define NB 1024

// fp32 buffers (zero-init device globals; pad rows never written)
__device__ float g_bx[7 * 130048];
__device__ float g_b0[5 * 650240];   // t0 conv0a out
__device__ float g_b2[5 * 82944];    // t2 Wr0 out
__device__ float g_x2[150 * 209920]; // x2 (Wa out, acc target)
__device__ float g_b9[512 * 55296];  // final pre-transpose

// bf16 hi/lo activations
__device__ __align__(16) __nv_bfloat16 g_bxh[7 * 130048],  g_bxl[7 * 130048];
__device__ __align__(16) __nv_bfloat16 g_t0h[5 * 650240],  g_t0l[5 * 650240];
__device__ __align__(16) __nv_bfloat16 g_t1h[5 * 580608],  g_t1l[5 * 580608];
__device__ __align__(16) __nv_bfloat16 g_x1h[25 * 580608], g_x1l[25 * 580608];
__device__ __align__(16) __nv_bfloat16 g_t3h[75 * 414720], g_t3l[75 * 414720];
__device__ __align__(16) __nv_bfloat16 g_t4h[75 * 293888], g_t4l[75 * 293888];
__device__ __align__(16) __nv_bfloat16 g_t5h[25 * 209920], g_t5l[25 * 209920];
__device__ __align__(16) __nv_bfloat16 g_x2h[150 * 209920], g_x2l[150 * 209920];
__device__ __align__(16) __nv_bfloat16 g_t6h[300 * 167936], g_t6l[300 * 167936];
__device__ __align__(16) __nv_bfloat16 g_t7h[300 * 73728], g_t7l[300 * 73728];
__device__ __align__(16) __nv_bfloat16 g_t8h[150 * 92160], g_t8l[150 * 92160];
// bf16 hi/lo weights (K padded to mult 16)
__device__ __align__(16) __nv_bfloat16 g_w1h[75 * 80],    g_w1l[75 * 80];
__device__ __align__(16) __nv_bfloat16 g_w2h[150 * 240],  g_w2l[150 * 240];
__device__ __align__(16) __nv_bfloat16 g_w3h[300 * 304],  g_w3l[300 * 304];
__device__ __align__(16) __nv_bfloat16 g_w4h[512 * 608],  g_w4l[512 * 608];
__device__ __align__(16) __nv_bfloat16 g_wbh[512 * 464],  g_wbl[512 * 464];
__device__ __align__(16) __nv_bfloat16 g_wl0h[81 * 128],  g_wl0l[81 * 128];
__device__ __align__(16) __nv_bfloat16 g_wr0h[81 * 128],  g_wr0l[81 * 128];
__device__ __align__(16) __nv_bfloat16 g_w0bh[25 * 16],   g_w0bl[25 * 16];
__device__ __align__(16) __nv_bfloat16 g_wl1h[41 * 96],   g_wl1l[41 * 96];
__device__ __align__(16) __nv_bfloat16 g_wrah[41 * 96],   g_wral[41 * 96];
__device__ __align__(16) __nv_bfloat16 g_wah[150 * 32],   g_wal[150 * 32];
__device__ __align__(16) __nv_bfloat16 g_wl2h[18 * 48],   g_wl2l[18 * 48];
__device__ __align__(16) __nv_bfloat16 g_wrbh[18 * 48],   g_wrbl[18 * 48];

__device__ __forceinline__ uint32_t s2u(const void* p) {
    uint32_t a;
    asm("{ .reg .u64 t; cvta.to.shared.u64 t, %1; cvt.u32.u64 %0, t; }" : "=r"(a) : "l"(p));
    return a;
}
#define SW128(o) ((o) ^ (((o) >> 3) & 0x70))
#define CP16(d, s) asm volatile("cp.async.cg.shared.global [%0], [%1], 16;" :: "r"(d), "l"(s))
__device__ __forceinline__ void zsts16(uint32_t d) {
    asm volatile("st.shared.v4.b32 [%0], {%1,%1,%1,%1};" :: "r"(d), "r"(0u));
}
#define LDMX4(r, a) \
    asm volatile("ldmatrix.sync.aligned.m8n8.x4.shared.b16 {%0,%1,%2,%3}, [%4];" \
        : "=r"((r)[0]), "=r"((r)[1]), "=r"((r)[2]), "=r"((r)[3]) : "r"(a))
#define LDMX4T(r, a) \
    asm volatile("ldmatrix.sync.aligned.m8n8.x4.trans.shared.b16 {%0,%1,%2,%3}, [%4];" \
        : "=r"((r)[0]), "=r"((r)[1]), "=r"((r)[2]), "=r"((r)[3]) : "r"(a))
#define MMA16816(c, a, b0, b1) \
    asm volatile("mma.sync.aligned.m16n8k16.row.col.f32.bf16.bf16.f32 " \
        "{%0,%1,%2,%3},{%4,%5,%6,%7},{%8,%9},{%0,%1,%2,%3};" \
        : "+f"((c)[0]), "+f"((c)[1]), "+f"((c)[2]), "+f"((c)[3]) \
        : "r"((a)[0]), "r"((a)[1]), "r"((a)[2]), "r"((a)[3]), "r"(b0), "r"(b1))

#define F_ACC  1
#define F_RELU 2
#define F_F32  4
#define F_HL   8
#define F_OUT  16

struct TP {
    const __nv_bfloat16 *Ah, *Al, *Xh, *Xl;
    const float* bias;
    float* C;
    __nv_bfloat16 *Ch, *Cl;
    const float* Y;
    const float* osc;
    const float* bias2;
    int M, K, Kp, KH, Hdiv, NC, flags;
    long long s_i, s_dh, xz_c, xz_h, cz_c, cz_h, c_ld;
};

__device__ __forceinline__ void tg_epi(const TP& p, float v0, float v1,
                                       long long rb, int n) {
    if (p.flags & F_F32)
        *reinterpret_cast<float2*>(&p.C[rb + n]) = make_float2(v0, v1);
    if (p.flags & F_HL) {
        __nv_bfloat16 h0 = __float2bfloat16(v0), h1 = __float2bfloat16(v1);
        __nv_bfloat162 hh; hh.x = h0; hh.y = h1;
        __nv_bfloat162 ll;
        ll.x = __float2bfloat16(v0 - __bfloat162float(h0));
        ll.y = __float2bfloat16(v1 - __bfloat162float(h1));
        *reinterpret_cast<__nv_bfloat162*>(&p.Ch[rb + n]) = hh;
        *reinterpret_cast<__nv_bfloat162*>(&p.Cl[rb + n]) = ll;
    }
}

// --- 256-thread kernel: CTA (32*MI)m x 128n x 64k, 8 warps 2mx4n, 2 CTAs/SM --
template<int MI>
__global__ __launch_bounds__(256, 2) void tgemm_k(TP p) {
    constexpr int A_HALF = MI * 4096;
    constexpr int XOFF = 2 * A_HALF;
    constexpr int STAGE = XOFF + 32768;
    extern __shared__ char sm_raw[];
    const uint32_t smb = s2u(sm_raw);
    const int tid = threadIdx.x;
    const int lane = tid & 31;
    const int warp_m = (tid >> 5) >> 2;
    const int warp_n = (tid >> 5) & 3;

    const int m0 = blockIdx.y * (MI * 32);
    const long long n0 = (long long)blockIdx.x * 128;
    const int zc = blockIdx.z / p.Hdiv, zh = blockIdx.z % p.Hdiv;
    const long long xzb = (long long)zc * p.xz_c + (long long)zh * p.xz_h;

    auto load_chunk = [&](int c, int b) {
        const uint32_t base = smb + b * STAGE;
        const int kc = c * 64;
#pragma unroll
        for (int i = 0; i < 2 * MI; i++) {
            int idx = tid + i * 256;
            int half = idx / (MI * 256), r = idx % (MI * 256);
            int m = r >> 3, k16 = r & 7;
            int gm = m0 + m, gk = kc + k16 * 8;
            uint32_t dst = base + half * A_HALF + SW128(m * 128 + k16 * 16);
            if (gm < p.M && gk < p.Kp)
                CP16(dst, (half ? p.Al : p.Ah) + (long long)gm * p.Kp + gk);
            else zsts16(dst);
        }
#pragma unroll
        for (int i = 0; i < 8; i++) {
            int idx = tid + i * 256;
            int half = idx >> 10, r = idx & 1023;
            int nblk = r >> 9, k = (r >> 3) & 63, n16 = r & 7;
            int gk = kc + k;
            uint32_t dst = base + XOFF + half * 16384 + nblk * 8192 + SW128(k * 128 + n16 * 16);
            if (gk < p.K) {
                long long ro = (long long)(gk / p.KH) * p.s_i + (long long)(gk % p.KH) * p.s_dh;
                CP16(dst, (half ? p.Xl : p.Xh) + xzb + ro + n0 + nblk * 64 + n16 * 8);
            } else zsts16(dst);
        }
        asm volatile("cp.async.commit_group;" ::: "memory");
    };

    float acc[MI][4][4];
#pragma unroll
    for (int a = 0; a < MI; a++)
#pragma unroll
        for (int b = 0; b < 4; b++)
#pragma unroll
            for (int r = 0; r < 4; r++) acc[a][b][r] = 0.f;

    load_chunk(0, 0);

    const int a_row = warp_m * (MI * 16) + (lane & 15);
    const int a_kb  = (lane >> 4) * 16;
    const int b_grp = lane >> 3, b_lr = lane & 7;
    const int b_k0  = (b_grp & 1) * 8 + b_lr;
    const int b_n   = warp_n * 32 + (b_grp >> 1) * 8;
    const int b_nblk = b_n >> 6, b_nin = b_n & 63;

    for (int c = 0; c < p.NC; c++) {
        if (c + 1 < p.NC) {
            load_chunk(c + 1, (c + 1) & 1);
            asm volatile("cp.async.wait_group 1;" ::: "memory");
        } else {
            asm volatile("cp.async.wait_group 0;" ::: "memory");
        }
        __syncthreads();
        const uint32_t base = smb + (c & 1) * STAGE;
#pragma unroll
        for (int s = 0; s < 4; s++) {
            uint32_t af[2][MI][4];
            uint32_t bf[2][2][4];
#pragma unroll
            for (int h = 0; h < 2; h++)
#pragma unroll
                for (int mi = 0; mi < MI; mi++) {
                    uint32_t ad = base + h * A_HALF
                        + SW128((a_row + mi * 16) * 128 + s * 32 + a_kb);
                    LDMX4(af[h][mi], ad);
                }
#pragma unroll
            for (int h = 0; h < 2; h++)
#pragma unroll
                for (int nj = 0; nj < 2; nj++) {
                    uint32_t ad = base + XOFF + h * 16384 + b_nblk * 8192
                        + SW128((s * 16 + b_k0) * 128 + (b_nin + nj * 16) * 2);
                    LDMX4T(bf[h][nj], ad);
                }
#pragma unroll
            for (int mi = 0; mi < MI; mi++)
#pragma unroll
                for (int n8 = 0; n8 < 4; n8++) {
                    int nj = n8 >> 1, pr = (n8 & 1) * 2;
                    MMA16816(acc[mi][n8], af[0][mi], bf[0][nj][pr], bf[0][nj][pr + 1]);
                    MMA16816(acc[mi][n8], af[0][mi], bf[1][nj][pr], bf[1][nj][pr + 1]);
                    MMA16816(acc[mi][n8], af[1][mi], bf[0][nj][pr], bf[0][nj][pr + 1]);
                }
        }
        __syncthreads();
    }

    const int g = lane >> 2, t4i = lane & 3;
    const long long czb = (long long)zc * p.cz_c + (long long)zh * p.cz_h + n0;
#pragma unroll
    for (int mi = 0; mi < MI; mi++)
#pragma unroll
        for (int part = 0; part < 2; part++) {
            int gm = m0 + warp_m * (MI * 16) + mi * 16 + g + part * 8;
            if (gm >= p.M) continue;
            float bs = p.bias[gm];
            float ow = 0.f;
            if (p.flags & F_OUT) { bs += p.bias2[gm]; ow = p.osc[gm]; }
            long long rb = czb + (long long)gm * p.c_ld;
#pragma unroll
            for (int n8 = 0; n8 < 4; n8++) {
                int n = warp_n * 32 + n8 * 8 + t4i * 2;
                float v0 = acc[mi][n8][part * 2] + bs;
                float v1 = acc[mi][n8][part * 2 + 1] + bs;
                if (p.flags & F_OUT) {
                    float2 y = *reinterpret_cast<const float2*>(&p.Y[czb + n]);
                    v0 += ow * y.x; v1 += ow * y.y;
                }
                if (p.flags & F_ACC) {
                    float2 o = *reinterpret_cast<const float2*>(&p.C[rb + n]);
                    v0 += o.x; v1 += o.y;
                }
                if (p.flags & F_RELU) { v0 = fmaxf(v0, 0.f); v1 = fmaxf(v1, 0.f); }
                tg_epi(p, v0, v1, rb, n);
            }
        }
}

// batched weight conversion
struct CvtJob { const float* src; __nv_bfloat16 *h, *l; int M, K, Kp; };
struct CvtBatch { CvtJob j[13]; };
__global__ void cvtall_k(CvtBatch b) {
    CvtJob jb = b.j[blockIdx.y];
    int i = blockIdx.x * 256 + threadIdx.x;
    if (i >= jb.M * jb.K) return;
    int m = i / jb.K, k = i % jb.K;
    float v = jb.src[i];
    __nv_bfloat16 hv = __float2bfloat16(v);
    jb.h[m * jb.Kp + k] = hv;
    jb.l[m * jb.Kp + k] = __float2bfloat16(v - __bfloat162float(hv));
}

struct GP {
    const float* __restrict__ A;
    const float* __restrict__ X;
    const float* __restrict__ bias;
    float* C;
    __nv_bfloat16 *Ch, *Cl;
    int M, K, KH, Hdiv, relu, accum, hl;
    long long s_i, s_dh, xz_c, xz_h, cz_c, cz_h, c_ld;
};

template<int BM, int TM>
__global__ __launch_bounds__(256) void gemm_k(GP p) {
    constexpr int BK = 16, BN = 128;
    __shared__ float As[BK][BM + 1];
    __shared__ float Xs[BK][BN];
    const int tid = threadIdx.x, cn = tid & 15, cm = tid >> 4;
    const int zc = blockIdx.z / p.Hdiv, zh = blockIdx.z % p.Hdiv;
    const float* Xb = p.X + (long long)zc * p.xz_c + (long long)zh * p.xz_h + (long long)blockIdx.x * BN;
    const long long czb = (long long)zc * p.cz_c + (long long)zh * p.cz_h + (long long)blockIdx.x * BN;
    const int m0 = blockIdx.y * BM;
    float r[TM][8];
#pragma unroll
    for (int i = 0; i < TM; i++)
#pragma unroll
        for (int j = 0; j < 8; j++) r[i][j] = 0.f;
    for (int kc = 0; kc < p.K; kc += BK) {
#pragma unroll
        for (int i = 0; i < BM * BK / 256; i++) {
            int idx = tid + i * 256, am = idx >> 4, ak = idx & 15;
            int gm = m0 + am, gk = kc + ak;
            float v = 0.f;
            if (gm < p.M && gk < p.K) v = p.A[(long long)gm * p.K + gk];
            As[ak][am] = v;
        }
#pragma unroll
        for (int i = 0; i < 2; i++) {
            int idx = tid + i * 256, xk = idx >> 5, xn = (idx & 31) << 2;
            int gk = kc + xk;
            float4 v = make_float4(0.f, 0.f, 0.f, 0.f);
            if (gk < p.K) {
                long long ro = (long long)(gk / p.KH) * p.s_i + (long long)(gk % p.KH) * p.s_dh;
                v = *reinterpret_cast<const float4*>(Xb + ro + xn);
            }
            *reinterpret_cast<float4*>(&Xs[xk][xn]) = v;
        }
        __syncthreads();
#pragma unroll
        for (int kk = 0; kk < BK; kk++) {
            float4 x0 = *reinterpret_cast<const float4*>(&Xs[kk][cn * 4]);
            float4 x1 = *reinterpret_cast<const float4*>(&Xs[kk][64 + cn * 4]);
            float a[TM];
#pragma unroll
            for (int i = 0; i < TM; i++) a[i] = As[kk][cm * TM + i];
#pragma unroll
            for (int i = 0; i < TM; i++) {
                r[i][0] = fmaf(a[i], x0.x, r[i][0]); r[i][1] = fmaf(a[i], x0.y, r[i][1]);
                r[i][2] = fmaf(a[i], x0.z, r[i][2]); r[i][3] = fmaf(a[i], x0.w, r[i][3]);
                r[i][4] = fmaf(a[i], x1.x, r[i][4]); r[i][5] = fmaf(a[i], x1.y, r[i][5]);
                r[i][6] = fmaf(a[i], x1.z, r[i][6]); r[i][7] = fmaf(a[i], x1.w, r[i][7]);
            }
        }
        __syncthreads();
    }
#pragma unroll
    for (int i = 0; i < TM; i++) {
        int gm = m0 + cm * TM + i;
        if (gm >= p.M) continue;
        float bs = p.bias[gm];
        long long rb = czb + (long long)gm * p.c_ld;
#pragma unroll
        for (int h = 0; h < 2; h++) {
            int n = h * 64 + cn * 4;
            float v[4] = { r[i][h * 4] + bs, r[i][h * 4 + 1] + bs,
                           r[i][h * 4 + 2] + bs, r[i][h * 4 + 3] + bs };
            if (p.accum) {
                float4 o = *reinterpret_cast<const float4*>(&p.C[rb + n]);
                v[0] += o.x; v[1] += o.y; v[2] += o.z; v[3] += o.w;
            }
            if (p.relu)
#pragma unroll
                for (int j = 0; j < 4; j++) v[j] = fmaxf(v[j], 0.f);
            *reinterpret_cast<float4*>(&p.C[rb + n]) = make_float4(v[0], v[1], v[2], v[3]);
            if (p.hl) {
#pragma unroll
                for (int j = 0; j < 4; j += 2) {
                    __nv_bfloat16 h0 = __float2bfloat16(v[j]), h1 = __float2bfloat16(v[j + 1]);
                    __nv_bfloat162 hh; hh.x = h0; hh.y = h1;
                    __nv_bfloat162 ll;
                    ll.x = __float2bfloat16(v[j] - __bfloat162float(h0));
                    ll.y = __float2bfloat16(v[j + 1] - __bfloat162float(h1));
                    *reinterpret_cast<__nv_bfloat162*>(&p.Ch[rb + n + j]) = hh;
                    *reinterpret_cast<__nv_bfloat162*>(&p.Cl[rb + n + j]) = ll;
                }
            }
        }
    }
}

__global__ void transpose_k(const float* __restrict__ in, float* __restrict__ out,
                            __nv_bfloat16* outh, __nv_bfloat16* outl, int R, int Cc) {
    __shared__ float t[32][33];
    int c0 = blockIdx.x * 32, r0 = blockIdx.y * 32;
    int c = c0 + threadIdx.x;
#pragma unroll
    for (int i = 0; i < 32; i += 8) {
        int rr = r0 + threadIdx.y + i;
        if (rr < R && c < Cc) t[threadIdx.y + i][threadIdx.x] = in[(long long)rr * Cc + c];
    }
    __syncthreads();
    int oc = r0 + threadIdx.x;
#pragma unroll
    for (int i = 0; i < 32; i += 8) {
        int orr = c0 + threadIdx.y + i;
        if (orr < Cc && oc < R) {
            float v = t[threadIdx.x][threadIdx.y + i];
            long long a = (long long)orr * R + oc;
            out[a] = v;
            if (outh) {
                __nv_bfloat16 hv = __float2bfloat16(v);
                outh[a] = hv;
                outl[a] = __float2bfloat16(v - __bfloat162float(hv));
            }
        }
    }
}

static void run_gemm(const float* A, const float* X, const float* bias, float* C,
                     __nv_bfloat16* Ch, __nv_bfloat16* Cl,
                     int M, int N, int K, int KH, int Z, int Hdiv,
                     long long s_i, long long s_dh, long long xz_c, long long xz_h,
                     long long cz_c, long long cz_h, long long c_ld, int relu, int accum) {
    GP p;
    p.A = A; p.X = X; p.bias = bias; p.C = C; p.Ch = Ch; p.Cl = Cl;
    p.M = M; p.K = K; p.KH = KH; p.Hdiv = Hdiv;
    p.s_i = s_i; p.s_dh = s_dh; p.xz_c = xz_c; p.xz_h = xz_h;
    p.cz_c = cz_c; p.cz_h = cz_h; p.c_ld = c_ld;
    p.relu = relu; p.accum = accum; p.hl = (Ch != nullptr);
    dim3 g(N / 128, (M + 15) / 16, Z);
    gemm_k<16, 1><<<g, 256>>>(p);
}

// mi: 1, 2 or 3; all at 2 CTAs/SM
static void run_tg(int mi, const __nv_bfloat16* Ah, const __nv_bfloat16* Al,
                   const __nv_bfloat16* Xh, const __nv_bfloat16* Xl,
                   const float* bias, float* C, __nv_bfloat16* Ch, __nv_bfloat16* Cl,
                   int M, int Nsl, int K, int Kp, int KH, int Z, int Hdiv,
                   long long s_i, long long s_dh, long long xz_c, long long xz_h,
                   long long cz_c, long long cz_h, long long c_ld, int flags,
                   const float* Y = nullptr, const float* osc = nullptr,
                   const float* bias2 = nullptr) {
    TP p;
    p.Ah = Ah; p.Al = Al; p.Xh = Xh; p.Xl = Xl; p.bias = bias;
    p.C = C; p.Ch = Ch; p.Cl = Cl;
    p.Y = Y; p.osc = osc; p.bias2 = bias2;
    p.M = M; p.K = K; p.Kp = Kp; p.KH = KH; p.Hdiv = Hdiv;
    p.NC = (Kp + 63) / 64; p.flags = flags;
    p.s_i = s_i; p.s_dh = s_dh; p.xz_c = xz_c; p.xz_h = xz_h;
    p.cz_c = cz_c; p.cz_h = cz_h; p.c_ld = c_ld;
    if (mi == 3) {
        dim3 g(Nsl / 128, (M + 95) / 96, Z);
        tgemm_k<3><<<g, 256, 114688>>>(p);
    } else if (mi == 2) {
        dim3 g(Nsl / 128, (M + 63) / 64, Z);
        tgemm_k<2><<<g, 256, 98304>>>(p);
    } else {
        dim3 g(Nsl / 128, (M + 31) / 32, Z);
        tgemm_k<1><<<g, 256, 81920>>>(p);
    }
}

extern "C" void kernel_launch(void* const* d_in, const int* in_sizes, int n_in,
                              void* d_out, int out_size) {
    const float* x   = (const float*)d_in[0];
    const float* W0a = (const float*)d_in[1];  const float* b0a = (const float*)d_in[2];
    const float* Wl0 = (const float*)d_in[3];  const float* bl0 = (const float*)d_in[4];
    const float* W0b = (const float*)d_in[5];  const float* b0b = (const float*)d_in[6];
    const float* Wr0 = (const float*)d_in[7];  const float* br0 = (const float*)d_in[8];
    const float* W0c = (const float*)d_in[9];  const float* b0c = (const float*)d_in[10];
    const float* W1  = (const float*)d_in[11]; const float* b1  = (const float*)d_in[12];
    const float* Wl1 = (const float*)d_in[13]; const float* bl1 = (const float*)d_in[14];
    const float* W2  = (const float*)d_in[15]; const float* b2  = (const float*)d_in[16];
    const float* Wra = (const float*)d_in[17]; const float* bra = (const float*)d_in[18];
    const float* Wa  = (const float*)d_in[19]; const float* ba  = (const float*)d_in[20];
    const float* W3  = (const float*)d_in[21]; const float* b3  = (const float*)d_in[22];
    const float* Wl2 = (const float*)d_in[23]; const float* bl2 = (const float*)d_in[24];
    const float* W4  = (const float*)d_in[25]; const float* b4  = (const float*)d_in[26];
    const float* Wrb = (const float*)d_in[27]; const float* brb = (const float*)d_in[28];
    const float* Wb  = (const float*)d_in[29]; const float* bb  = (const float*)d_in[30];
    float* out = (float*)d_out;

    cudaFuncSetAttribute(tgemm_k<3>, cudaFuncAttributeMaxDynamicSharedMemorySize, 114688);
    cudaFuncSetAttribute(tgemm_k<2>, cudaFuncAttributeMaxDynamicSharedMemorySize, 98304);
    cudaFuncSetAttribute(tgemm_k<1>, cudaFuncAttributeMaxDynamicSharedMemorySize, 81920);

    float *bx, *t0, *t2, *x2, *t9;
    cudaGetSymbolAddress((void**)&bx, g_bx);  cudaGetSymbolAddress((void**)&t0, g_b0);
    cudaGetSymbolAddress((void**)&t2, g_b2);  cudaGetSymbolAddress((void**)&x2, g_x2);
    cudaGetSymbolAddress((void**)&t9, g_b9);
    __nv_bfloat16 *bxh, *bxl, *t0h, *t0l, *t1h, *t1l, *x1h, *x1l, *t3h, *t3l, *t4h, *t4l;
    __nv_bfloat16 *t5h, *t5l, *x2h, *x2l, *t6h, *t6l, *t7h, *t7l, *t8h, *t8l;
    cudaGetSymbolAddress((void**)&bxh, g_bxh); cudaGetSymbolAddress((void**)&bxl, g_bxl);
    cudaGetSymbolAddress((void**)&t0h, g_t0h); cudaGetSymbolAddress((void**)&t0l, g_t0l);
    cudaGetSymbolAddress((void**)&t1h, g_t1h); cudaGetSymbolAddress((void**)&t1l, g_t1l);
    cudaGetSymbolAddress((void**)&x1h, g_x1h); cudaGetSymbolAddress((void**)&x1l, g_x1l);
    cudaGetSymbolAddress((void**)&t3h, g_t3h); cudaGetSymbolAddress((void**)&t3l, g_t3l);
    cudaGetSymbolAddress((void**)&t4h, g_t4h); cudaGetSymbolAddress((void**)&t4l, g_t4l);
    cudaGetSymbolAddress((void**)&t5h, g_t5h); cudaGetSymbolAddress((void**)&t5l, g_t5l);
    cudaGetSymbolAddress((void**)&x2h, g_x2h); cudaGetSymbolAddress((void**)&x2l, g_x2l);
    cudaGetSymbolAddress((void**)&t6h, g_t6h); cudaGetSymbolAddress((void**)&t6l, g_t6l);
    cudaGetSymbolAddress((void**)&t7h, g_t7h); cudaGetSymbolAddress((void**)&t7l, g_t7l);
    cudaGetSymbolAddress((void**)&t8h, g_t8h); cudaGetSymbolAddress((void**)&t8l, g_t8l);
    __nv_bfloat16 *w1h, *w1l, *w2h, *w2l, *w3h, *w3l, *w4h, *w4l, *wbh, *wbl;
    __nv_bfloat16 *wl0h, *wl0l, *wr0h, *wr0l, *w0bh, *w0bl;
    __nv_bfloat16 *wl1h, *wl1l, *wrah, *wral, *wah, *wal, *wl2h, *wl2l, *wrbh, *wrbl;
    cudaGetSymbolAddress((void**)&w1h, g_w1h);   cudaGetSymbolAddress((void**)&w1l, g_w1l);
    cudaGetSymbolAddress((void**)&w2h, g_w2h);   cudaGetSymbolAddress((void**)&w2l, g_w2l);
    cudaGetSymbolAddress((void**)&w3h, g_w3h);   cudaGetSymbolAddress((void**)&w3l, g_w3l);
    cudaGetSymbolAddress((void**)&w4h, g_w4h);   cudaGetSymbolAddress((void**)&w4l, g_w4l);
    cudaGetSymbolAddress((void**)&wbh, g_wbh);   cudaGetSymbolAddress((void**)&wbl, g_wbl);
    cudaGetSymbolAddress((void**)&wl0h, g_wl0h); cudaGetSymbolAddress((void**)&wl0l, g_wl0l);
    cudaGetSymbolAddress((void**)&wr0h, g_wr0h); cudaGetSymbolAddress((void**)&wr0l, g_wr0l);
    cudaGetSymbolAddress((void**)&w0bh, g_w0bh); cudaGetSymbolAddress((void**)&w0bl, g_w0bl);
    cudaGetSymbolAddress((void**)&wl1h, g_wl1h); cudaGetSymbolAddress((void**)&wl1l, g_wl1l);
    cudaGetSymbolAddress((void**)&wrah, g_wrah); cudaGetSymbolAddress((void**)&wral, g_wral);
    cudaGetSymbolAddress((void**)&wah, g_wah);   cudaGetSymbolAddress((void**)&wal, g_wal);
    cudaGetSymbolAddress((void**)&wl2h, g_wl2h); cudaGetSymbolAddress((void**)&wl2l, g_wl2l);
    cudaGetSymbolAddress((void**)&wrbh, g_wrbh); cudaGetSymbolAddress((void**)&wrbl, g_wrbl);

    // launch 1: input transpose
    { dim3 g((635 + 31) / 32, 32), b(32, 8);
      transpose_k<<<g, b>>>(x, bx + 130048, bxh + 130048, bxl + 130048, NB, 635); }
    // launch 2: all weight conversions
    {
        CvtBatch cb;
        cb.j[0]  = { W1,  w1h,  w1l,  75, 75, 80 };
        cb.j[1]  = { W2,  w2h,  w2l,  150, 225, 240 };
        cb.j[2]  = { W3,  w3h,  w3l,  300, 300, 304 };
        cb.j[3]  = { W4,  w4h,  w4l,  512, 600, 608 };
        cb.j[4]  = { Wb,  wbh,  wbl,  512, 450, 464 };
        cb.j[5]  = { Wl0, wl0h, wl0l, 81, 127, 128 };
        cb.j[6]  = { Wr0, wr0h, wr0l, 81, 127, 128 };
        cb.j[7]  = { W0b, w0bh, w0bl, 25, 15, 16 };
        cb.j[8]  = { Wl1, wl1h, wl1l, 41, 81, 96 };
        cb.j[9]  = { Wra, wrah, wral, 41, 81, 96 };
        cb.j[10] = { Wa,  wah,  wal,  150, 25, 32 };
        cb.j[11] = { Wl2, wl2h, wl2l, 18, 41, 48 };
        cb.j[12] = { Wrb, wrbh, wrbl, 18, 41, 48 };
        dim3 g(1200, 13);
        cvtall_k<<<g, 256>>>(cb);
    }
    // launch 3: conv0a (fp32) -> t0 + h/l
    run_gemm(W0a, bx, b0a, t0, t0h, t0l, 5, 130048, 3, 3, 5, 5,
             910336, 130048, 0, 130048, 0, 130048, 650240, 0, 0);
    // launch 4 (PROFILED): Wl0 (tensor MI3, relu) -> t1 h/l
    run_tg(3, wl0h, wl0l, t0h, t0l, bl0, nullptr, t1h + 82944, t1l + 82944,
           81, NB, 127, 128, 1, 25, 5, 1024, 0, 650240, 130048,
           580608, 82944, 1024, F_HL | F_RELU);
    // launch 5: Wr0 (tensor MI3) -> t2 fp32
    run_tg(3, wr0h, wr0l, bxh + 130048, bxl + 130048, br0, t2, nullptr, nullptr,
           81, NB, 127, 128, 1, 5, 5, 1024, 0, 0, 130048,
           0, 82944, 1024, F_F32);
    // launch 6: W0b (tensor MI1) + fused W0c outer-product -> x1 h/l
    run_tg(1, w0bh, w0bl, t1h, t1l, b0b, nullptr, x1h + 82944, x1l + 82944,
           25, 82944, 15, 16, 3, 5, 5, 580608, 82944, 0, 82944,
           0, 82944, 580608, F_OUT | F_HL, t2, W0c, b0c);
    // W1 (tensor MI3) -> t3 h/l
    run_tg(3, w1h, w1l, x1h, x1l, b1, nullptr, t3h, t3l,
           75, 82944, 75, 80, 3, 5, 5, 580608, 82944, 0, 82944,
           0, 82944, 414720, F_HL);
    // Wl1 (tensor MI2, relu) -> t4 h/l
    run_tg(2, wl1h, wl1l, t3h, t3l, bl1, nullptr, t4h + 41984, t4l + 41984,
           41, NB, 81, 96, 1, 375, 5, 1024, 0, 414720, 82944,
           293888, 41984, 1024, F_HL | F_RELU);
    // Wra (tensor MI2) -> t5 h/l
    run_tg(2, wrah, wral, x1h + 82944, x1l + 82944, bra, nullptr, t5h, t5l,
           41, NB, 81, 96, 1, 125, 5, 1024, 0, 580608, 82944,
           209920, 41984, 1024, F_HL);
    // Wa (tensor MI3, 1x1) -> x2 fp32
    run_tg(3, wah, wal, t5h, t5l, ba, x2, nullptr, nullptr,
           150, 41984, 25, 32, 1, 5, 5, 209920, 0, 0, 41984,
           0, 41984, 209920, F_F32);
    // W2 (tensor MI3, ACC) -> x2 h/l
    run_tg(3, w2h, w2l, t4h, t4l, b2, x2, x2h, x2l,
           150, 41984, 225, 240, 3, 5, 5, 293888, 41984, 0, 41984,
           0, 41984, 209920, F_ACC | F_HL);
    // W3 (tensor MI2) -> t6 h/l
    run_tg(2, w3h, w3l, x2h, x2l, b3, nullptr, t6h, t6l,
           300, 41984, 300, 304, 2, 4, 4, 209920, 41984, 0, 41984,
           0, 41984, 167936, F_HL);
    // Wl2 (tensor MI1, relu) -> t7 h/l
    run_tg(1, wl2h, wl2l, t6h, t6l, bl2, nullptr, t7h, t7l,
           18, NB, 41, 48, 1, 1200, 4, 1024, 0, 167936, 41984,
           73728, 18432, 1024, F_HL | F_RELU);
    // Wrb (tensor MI1) -> t8 h/l
    run_tg(1, wrbh, wrbl, x2h, x2l, brb, nullptr, t8h, t8l,
           18, NB, 41, 48, 1, 750, 5, 1024, 0, 209920, 41984,
           92160, 18432, 1024, F_HL);
    // Wb (tensor MI2) -> t9 fp32
    run_tg(2, wbh, wbl, t8h, t8l, bb, t9, nullptr, nullptr,
           512, 18432, 450, 464, 3, 3, 3, 92160, 18432, 0, 18432,
           0, 18432, 55296, F_F32);
    // W4 (tensor MI2, ACC) -> t9 fp32
    run_tg(2, w4h, w4l, t7h, t7l, b4, t9, nullptr, nullptr,
           512, 18432, 600, 608, 2, 3, 3, 73728, 18432, 0, 18432,
           0, 18432, 55296, F_F32 | F_ACC);
    // final transpose
    { dim3 g(32, (27648 + 31) / 32), b(32, 8);
      transpose_k<<<g, b>>>(t9, out, nullptr, nullptr, 27648, NB); }
    (void)in_sizes; (void)n_in; (void)out_size;
}